// round 1
// baseline (speedup 1.0000x reference)
#include <cuda_runtime.h>
#include <math.h>

#define Bb 4
#define Lq 1024
#define Dd 1024
#define Hh 8
#define Pp 1024
#define Ff 4096
#define DKc 128

// ---------------- scratch (no allocs allowed) ----------------
__device__ float g_xn[Bb*Lq*Dd];                   // LN output (reused)
__device__ float g_q [Bb*Hh*Lq*DKc];               // Q [B,H,L,DK]; reused as attn-out
__device__ float g_k [Bb*Hh*Lq*DKc];
__device__ float g_v [Bb*Hh*Lq*DKc];
__device__ float g_x [Bb*Lq*Dd];                   // residual-1 output
__device__ float g_h [Bb*Lq*Ff];                   // FFN hidden
__device__ float g_scores[(size_t)Bb*Hh*Lq*Lq];    // scores -> attn (in place)
__device__ float g_qr    [(size_t)Bb*Hh*Lq*Pp];    // qr -> attn_path (reused)

// ---------------- LayerNorm ----------------
__global__ void ln_kernel(const float* __restrict__ x, const float* __restrict__ g,
                          const float* __restrict__ b, float* __restrict__ y){
  __shared__ float red[256];
  int row = blockIdx.x;
  const float* xr = x + (size_t)row*Dd;
  float v[4]; float s = 0.f;
#pragma unroll
  for(int i=0;i<4;i++){ v[i] = xr[threadIdx.x + i*256]; s += v[i]; }
  red[threadIdx.x] = s; __syncthreads();
  for(int o=128;o>0;o>>=1){ if(threadIdx.x<o) red[threadIdx.x]+=red[threadIdx.x+o]; __syncthreads(); }
  float mean = red[0]*(1.f/Dd); __syncthreads();
  float s2 = 0.f;
#pragma unroll
  for(int i=0;i<4;i++){ float d = v[i]-mean; s2 += d*d; }
  red[threadIdx.x] = s2; __syncthreads();
  for(int o=128;o>0;o>>=1){ if(threadIdx.x<o) red[threadIdx.x]+=red[threadIdx.x+o]; __syncthreads(); }
  float inv = rsqrtf(red[0]*(1.f/Dd) + 1e-6f);
  float* yr = y + (size_t)row*Dd;
#pragma unroll
  for(int i=0;i<4;i++){ int c = threadIdx.x + i*256; yr[c] = g[c]*(v[i]-mean)*inv + b[c]; }
}

// ---------------- generic SGEMM (row-major A[M,K] @ W[K,N]) ----------------
#define EPI_PLAIN 0
#define EPI_QKV   1
#define EPI_RES   2
#define EPI_GELU  3

template<int MODE>
__global__ void sgemm(const float* __restrict__ A, const float* __restrict__ W,
                      const float* __restrict__ bias, const float* __restrict__ res,
                      float* __restrict__ C, int M, int N, int K){
  __shared__ float As[8][128];
  __shared__ float Ws[8][128];
  int tid = threadIdx.x;
  int br = blockIdx.y*128, bc = blockIdx.x*128;
  int tx = tid & 15, ty = tid >> 4;
  float acc[8][8] = {};
  int arow = tid >> 1, acol = (tid & 1)*4;
  int wrow = tid >> 5, wcol = (tid & 31)*4;
  const float* Aptr = A + (size_t)(br+arow)*K + acol;
  const float* Wptr = W + (size_t)wrow*N + bc + wcol;
  for(int k0=0;k0<K;k0+=8){
    float4 av = *(const float4*)(Aptr + k0);
    As[acol+0][arow]=av.x; As[acol+1][arow]=av.y; As[acol+2][arow]=av.z; As[acol+3][arow]=av.w;
    float4 wv = *(const float4*)(Wptr + (size_t)k0*N);
    *(float4*)&Ws[wrow][wcol] = wv;
    __syncthreads();
#pragma unroll
    for(int kk=0;kk<8;kk++){
      float a[8], b[8];
      *(float4*)(a)   = *(float4*)&As[kk][ty*8];
      *(float4*)(a+4) = *(float4*)&As[kk][ty*8+4];
      *(float4*)(b)   = *(float4*)&Ws[kk][tx*8];
      *(float4*)(b+4) = *(float4*)&Ws[kk][tx*8+4];
#pragma unroll
      for(int i=0;i<8;i++)
#pragma unroll
        for(int j=0;j<8;j++) acc[i][j] += a[i]*b[j];
    }
    __syncthreads();
  }
#pragma unroll
  for(int i=0;i<8;i++){
    int r = br + ty*8 + i;
#pragma unroll
    for(int j=0;j<8;j++){
      int c = bc + tx*8 + j;
      float val = acc[i][j] + bias[c];
      if(MODE==EPI_RES) val += res[(size_t)r*N + c];
      if(MODE==EPI_GELU){
        float u = val;
        val = 0.5f*u*(1.f + tanhf(0.7978845608028654f*(u + 0.044715f*u*u*u)));
      }
      if(MODE==EPI_QKV){
        int bi = r >> 10, l = r & 1023, h = c >> 7, d = c & 127;
        C[(((size_t)(bi*Hh+h))*Lq + l)*DKc + d] = val;
      } else {
        C[(size_t)r*N + c] = val;
      }
    }
  }
}

// ---------------- batched NT GEMM: C[bh] = A[bh][L,128] @ B[bh][N,128]^T ----------------
__global__ void gemm_nt(const float* __restrict__ Qb, const float* __restrict__ Kb,
                        float* __restrict__ Cb, int Nrows){
  int bh = blockIdx.z;
  const float* A  = Qb + (size_t)bh*Lq*DKc;
  const float* Bm = Kb + (size_t)bh*Nrows*DKc;
  float* C = Cb + (size_t)bh*Lq*Nrows;
  __shared__ float As[8][128];
  __shared__ float Bs[8][128];
  int tid = threadIdx.x;
  int br = blockIdx.y*128, bc = blockIdx.x*128;
  int tx = tid & 15, ty = tid >> 4;
  float acc[8][8] = {};
  int lrow = tid >> 1, lcol = (tid & 1)*4;
  for(int k0=0;k0<DKc;k0+=8){
    float4 av = *(const float4*)(A + (size_t)(br+lrow)*DKc + k0 + lcol);
    As[lcol+0][lrow]=av.x; As[lcol+1][lrow]=av.y; As[lcol+2][lrow]=av.z; As[lcol+3][lrow]=av.w;
    float4 bv = *(const float4*)(Bm + (size_t)(bc+lrow)*DKc + k0 + lcol);
    Bs[lcol+0][lrow]=bv.x; Bs[lcol+1][lrow]=bv.y; Bs[lcol+2][lrow]=bv.z; Bs[lcol+3][lrow]=bv.w;
    __syncthreads();
#pragma unroll
    for(int kk=0;kk<8;kk++){
      float a[8], b[8];
      *(float4*)(a)   = *(float4*)&As[kk][ty*8];
      *(float4*)(a+4) = *(float4*)&As[kk][ty*8+4];
      *(float4*)(b)   = *(float4*)&Bs[kk][tx*8];
      *(float4*)(b+4) = *(float4*)&Bs[kk][tx*8+4];
#pragma unroll
      for(int i=0;i<8;i++)
#pragma unroll
        for(int j=0;j<8;j++) acc[i][j] += a[i]*b[j];
    }
    __syncthreads();
  }
#pragma unroll
  for(int i=0;i<8;i++){
    int r = br + ty*8 + i;
#pragma unroll
    for(int j=0;j<8;j++)
      C[(size_t)r*Nrows + bc + tx*8 + j] = acc[i][j];
  }
}

// ---------------- fused gather + scale + ap + mask + softmax ----------------
__global__ void softmax_kernel(float* __restrict__ scores, const float* __restrict__ qr,
                               const int* __restrict__ pm, const int* __restrict__ mask,
                               const float* __restrict__ ap){
  __shared__ float red[256];
  int bh = blockIdx.y;
  int b  = bh / Hh;
  int i  = blockIdx.x;
  float* srow = scores + ((size_t)bh*Lq + i)*Lq;
  const float* qrow = qr + ((size_t)bh*Lq + i)*Pp;
  const int*   prow = pm + ((size_t)b*Lq + i)*Lq;
  const int*   mrow = mask + ((size_t)b*Lq + i)*Lq;
  const float* arow = ap + ((size_t)bh*Lq + i)*Lq;
  const float scale = 0.08838834764831845f; // 1/sqrt(128)
  float v[4]; float mx = -3.0e38f;
#pragma unroll
  for(int k=0;k<4;k++){
    int j = threadIdx.x + k*256;
    float val;
    if(mrow[j]==0) val = -1e9f;
    else           val = (srow[j] + qrow[prow[j]])*scale + arow[j];
    v[k] = val; mx = fmaxf(mx, val);
  }
  red[threadIdx.x] = mx; __syncthreads();
  for(int o=128;o>0;o>>=1){ if(threadIdx.x<o) red[threadIdx.x]=fmaxf(red[threadIdx.x],red[threadIdx.x+o]); __syncthreads(); }
  mx = red[0]; __syncthreads();
  float s = 0.f;
#pragma unroll
  for(int k=0;k<4;k++){ v[k] = expf(v[k]-mx); s += v[k]; }
  red[threadIdx.x] = s; __syncthreads();
  for(int o=128;o>0;o>>=1){ if(threadIdx.x<o) red[threadIdx.x]+=red[threadIdx.x+o]; __syncthreads(); }
  float inv = 1.f/red[0];
#pragma unroll
  for(int k=0;k<4;k++) srow[threadIdx.x + k*256] = v[k]*inv;
}

// ---------------- scatter attn into path buckets ----------------
__global__ void scatter_kernel(const float* __restrict__ attn, const int* __restrict__ pm,
                               float* __restrict__ path){
  __shared__ float sp[Pp];
  int bh = blockIdx.y;
  int b  = bh / Hh;
  int i  = blockIdx.x;
#pragma unroll
  for(int k=0;k<4;k++) sp[threadIdx.x + k*256] = 0.f;
  __syncthreads();
  const float* arow = attn + ((size_t)bh*Lq + i)*Lq;
  const int*   prow = pm   + ((size_t)b*Lq + i)*Lq;
#pragma unroll
  for(int k=0;k<4;k++){
    int j = threadIdx.x + k*256;
    atomicAdd(&sp[prow[j]], arow[j]);
  }
  __syncthreads();
  float* orow = path + ((size_t)bh*Lq + i)*Pp;
#pragma unroll
  for(int k=0;k<4;k++){ int c = threadIdx.x + k*256; orow[c] = sp[c]; }
}

// ---------------- out = attn@v + attn_path@r_v (batched, N=128) ----------------
__global__ void out_gemm(const float* __restrict__ attn, const float* __restrict__ vb,
                         const float* __restrict__ path, const float* __restrict__ rvb,
                         float* __restrict__ outb){
  int bh = blockIdx.z;
  int br = blockIdx.y*128;
  __shared__ float As[8][128];
  __shared__ float Ws[8][128];
  int tid = threadIdx.x, tx = tid & 15, ty = tid >> 4;
  float acc[8][8] = {};
  int arow = tid >> 1, acol = (tid & 1)*4;
  int wrow = tid >> 5, wcol = (tid & 31)*4;
  for(int ph=0; ph<2; ph++){
    const float* A = ph ? (path + (size_t)bh*Lq*Pp)  : (attn + (size_t)bh*Lq*Lq);
    const float* W = ph ? (rvb  + (size_t)bh*Pp*DKc) : (vb   + (size_t)bh*Lq*DKc);
    for(int k0=0;k0<Lq;k0+=8){
      float4 av = *(const float4*)(A + (size_t)(br+arow)*Lq + k0 + acol);
      As[acol+0][arow]=av.x; As[acol+1][arow]=av.y; As[acol+2][arow]=av.z; As[acol+3][arow]=av.w;
      float4 wv = *(const float4*)(W + (size_t)(k0+wrow)*DKc + wcol);
      *(float4*)&Ws[wrow][wcol] = wv;
      __syncthreads();
#pragma unroll
      for(int kk=0;kk<8;kk++){
        float a[8], b[8];
        *(float4*)(a)   = *(float4*)&As[kk][ty*8];
        *(float4*)(a+4) = *(float4*)&As[kk][ty*8+4];
        *(float4*)(b)   = *(float4*)&Ws[kk][tx*8];
        *(float4*)(b+4) = *(float4*)&Ws[kk][tx*8+4];
#pragma unroll
        for(int i=0;i<8;i++)
#pragma unroll
          for(int j=0;j<8;j++) acc[i][j] += a[i]*b[j];
      }
      __syncthreads();
    }
  }
#pragma unroll
  for(int i=0;i<8;i++)
#pragma unroll
    for(int j=0;j<8;j++)
      outb[(size_t)bh*Lq*DKc + (size_t)(br+ty*8+i)*DKc + tx*8 + j] = acc[i][j];
}

// ---------------- merge heads [B,H,L,DK] -> [B,L,D] ----------------
__global__ void merge_heads(const float* __restrict__ in, float* __restrict__ out){
  int idx = blockIdx.x*256 + threadIdx.x;   // 0 .. B*H*L*DK-1 (2^22)
  int d = idx & 127;
  int l = (idx >> 7) & 1023;
  int h = (idx >> 17) & 7;
  int b = idx >> 20;
  out[((size_t)(b*Lq + l))*Dd + h*DKc + d] = in[idx];
}

// ---------------- launch ----------------
extern "C" void kernel_launch(void* const* d_in, const int* in_sizes, int n_in,
                              void* d_out, int out_size){
  const float* content = (const float*)d_in[0];
  const int*   mask    = (const int*)  d_in[1];
  const float* r_k     = (const float*)d_in[2];
  const float* r_v     = (const float*)d_in[3];
  const int*   path_map= (const int*)  d_in[4];
  const float* ap      = (const float*)d_in[5];
  const float* wq = (const float*)d_in[6];  const float* bq = (const float*)d_in[7];
  const float* wk = (const float*)d_in[8];  const float* bk = (const float*)d_in[9];
  const float* wv = (const float*)d_in[10]; const float* bv = (const float*)d_in[11];
  const float* wo = (const float*)d_in[12]; const float* bo = (const float*)d_in[13];
  const float* ln1g = (const float*)d_in[14]; const float* ln1b = (const float*)d_in[15];
  const float* ln2g = (const float*)d_in[16]; const float* ln2b = (const float*)d_in[17];
  const float* w1 = (const float*)d_in[18]; const float* b1 = (const float*)d_in[19];
  const float* w2 = (const float*)d_in[20]; const float* b2 = (const float*)d_in[21];
  float* out = (float*)d_out;

  float *xn,*q,*k,*v,*x,*h,*sc,*qr;
  cudaGetSymbolAddress((void**)&xn, g_xn);
  cudaGetSymbolAddress((void**)&q,  g_q);
  cudaGetSymbolAddress((void**)&k,  g_k);
  cudaGetSymbolAddress((void**)&v,  g_v);
  cudaGetSymbolAddress((void**)&x,  g_x);
  cudaGetSymbolAddress((void**)&h,  g_h);
  cudaGetSymbolAddress((void**)&sc, g_scores);
  cudaGetSymbolAddress((void**)&qr, g_qr);

  // 1) LN1
  ln_kernel<<<Bb*Lq, 256>>>(content, ln1g, ln1b, xn);
  // 2) QKV projections (head-layout epilogue)
  dim3 gqkv(Dd/128, (Bb*Lq)/128);
  sgemm<EPI_QKV><<<gqkv,256>>>(xn, wq, bq, nullptr, q, Bb*Lq, Dd, Dd);
  sgemm<EPI_QKV><<<gqkv,256>>>(xn, wk, bk, nullptr, k, Bb*Lq, Dd, Dd);
  sgemm<EPI_QKV><<<gqkv,256>>>(xn, wv, bv, nullptr, v, Bb*Lq, Dd, Dd);
  // 3) scores = q@k^T ; qr = q@r_k^T (batched over B*H)
  dim3 gnt(Lq/128, Lq/128, Bb*Hh);
  gemm_nt<<<gnt,256>>>(q, k,  sc, Lq);
  gemm_nt<<<gnt,256>>>(q, r_k, qr, Pp);
  // 4) fused gather + scale + ap + mask + softmax (attn in place in sc)
  softmax_kernel<<<dim3(Lq, Bb*Hh),256>>>(sc, qr, path_map, mask, ap);
  // 5) scatter attn into path buckets (qr reused as attn_path)
  scatter_kernel<<<dim3(Lq, Bb*Hh),256>>>(sc, path_map, qr);
  // 6) out = attn@v + attn_path@r_v   (q reused as output)
  out_gemm<<<dim3(1, Lq/128, Bb*Hh),256>>>(sc, v, qr, r_v, q);
  // 7) merge heads -> xn
  merge_heads<<<(Bb*Hh*Lq*DKc)/256, 256>>>(q, xn);
  // 8) x = xn@wo + bo + content
  sgemm<EPI_RES><<<dim3(Dd/128,(Bb*Lq)/128),256>>>(xn, wo, bo, content, x, Bb*Lq, Dd, Dd);
  // 9) LN2
  ln_kernel<<<Bb*Lq, 256>>>(x, ln2g, ln2b, xn);
  // 10) h = gelu(xn@w1 + b1)
  sgemm<EPI_GELU><<<dim3(Ff/128,(Bb*Lq)/128),256>>>(xn, w1, b1, nullptr, h, Bb*Lq, Ff, Dd);
  // 11) out = h@w2 + b2 + x
  sgemm<EPI_RES><<<dim3(Dd/128,(Bb*Lq)/128),256>>>(h, w2, b2, x, out, Bb*Lq, Dd, Ff);
}

// round 4
// speedup vs baseline: 2.1466x; 2.1466x over previous
#include <cuda_runtime.h>
#include <cuda_bf16.h>
#include <cstdint>
#include <math.h>

typedef __nv_bfloat16 bf;

#define Bb 4
#define Lq 1024
#define Dd 1024
#define Hh 8
#define Pp 1024
#define Ff 4096
#define DKc 128

// ---------------- scratch ----------------
__device__ bf g_xn_h[Bb*Lq*Dd], g_xn_l[Bb*Lq*Dd];
__device__ bf g_q_h[Bb*Hh*Lq*DKc], g_q_l[Bb*Hh*Lq*DKc];
__device__ bf g_k_h[Bb*Hh*Lq*DKc], g_k_l[Bb*Hh*Lq*DKc];
__device__ bf g_v_h[Bb*Hh*Lq*DKc], g_v_l[Bb*Hh*Lq*DKc];
__device__ bf g_vt_h[Bb*Hh*Lq*DKc], g_vt_l[Bb*Hh*Lq*DKc];
__device__ bf g_h_h[Bb*Lq*Ff], g_h_l[Bb*Lq*Ff];
__device__ bf g_attn_h[(size_t)Bb*Hh*Lq*Lq], g_attn_l[(size_t)Bb*Hh*Lq*Lq];
__device__ bf g_path_h[(size_t)Bb*Hh*Lq*Pp], g_path_l[(size_t)Bb*Hh*Lq*Pp];
__device__ bf g_wqt_h[Dd*Dd], g_wqt_l[Dd*Dd];
__device__ bf g_wkt_h[Dd*Dd], g_wkt_l[Dd*Dd];
__device__ bf g_wvt_h[Dd*Dd], g_wvt_l[Dd*Dd];
__device__ bf g_wot_h[Dd*Dd], g_wot_l[Dd*Dd];
__device__ bf g_w1t_h[Dd*Ff], g_w1t_l[Dd*Ff];
__device__ bf g_w2t_h[Dd*Ff], g_w2t_l[Dd*Ff];
__device__ bf g_rk_h[Bb*Hh*Pp*DKc], g_rk_l[Bb*Hh*Pp*DKc];
__device__ bf g_rvt_h[Bb*Hh*Pp*DKc], g_rvt_l[Bb*Hh*Pp*DKc];
__device__ float g_scores[(size_t)Bb*Hh*Lq*Lq];
__device__ float g_qr[(size_t)Bb*Hh*Lq*Pp];
__device__ float g_aout[Bb*Hh*Lq*DKc];
__device__ float g_x[Bb*Lq*Dd];

// ---------------- helpers ----------------
__device__ __forceinline__ void ldsm4(uint32_t r[4], const bf* p){
  uint32_t a = (uint32_t)__cvta_generic_to_shared(p);
  asm volatile("ldmatrix.sync.aligned.m8n8.x4.shared.b16 {%0,%1,%2,%3},[%4];"
    :"=r"(r[0]),"=r"(r[1]),"=r"(r[2]),"=r"(r[3]):"r"(a));
}
__device__ __forceinline__ void mma_bf16(float c[4], const uint32_t a[4], const uint32_t b[2]){
  asm volatile("mma.sync.aligned.m16n8k16.row.col.f32.bf16.bf16.f32 "
    "{%0,%1,%2,%3},{%4,%5,%6,%7},{%8,%9},{%0,%1,%2,%3};"
    :"+f"(c[0]),"+f"(c[1]),"+f"(c[2]),"+f"(c[3])
    :"r"(a[0]),"r"(a[1]),"r"(a[2]),"r"(a[3]),"r"(b[0]),"r"(b[1]));
}
__device__ __forceinline__ void split_write(bf* H, bf* L, long o, float v0, float v1){
  bf h0 = __float2bfloat16(v0), h1 = __float2bfloat16(v1);
  bf l0 = __float2bfloat16(v0 - __bfloat162float(h0));
  bf l1 = __float2bfloat16(v1 - __bfloat162float(h1));
  __nv_bfloat162 hh; hh.x = h0; hh.y = h1;
  __nv_bfloat162 ll; ll.x = l0; ll.y = l1;
  *(__nv_bfloat162*)&H[o] = hh;
  *(__nv_bfloat162*)&L[o] = ll;
}
__device__ __forceinline__ float gelu_f(float u){
  return 0.5f*u*(1.f + tanhf(0.7978845608028654f*(u + 0.044715f*u*u*u)));
}

// ---------------- split-bf16 tensor-core GEMM ----------------
// A[M][K] hi/lo (row-major), B[N][K] hi/lo (row-major = pre-transposed), C epilogue by MODE
#define M_F32  0
#define M_ACC  1
#define M_QKV  2
#define M_GELU 3
#define M_RES  4

#define PITCH 40

template<int MODE>
__global__ __launch_bounds__(256)
void hgemm(const bf* __restrict__ Ah, const bf* __restrict__ Al,
           const bf* __restrict__ Bh, const bf* __restrict__ Bl,
           const float* __restrict__ bias, const float* __restrict__ res,
           float* __restrict__ Cf, bf* __restrict__ Ch, bf* __restrict__ Cl,
           int M, int N, int K, long sA, long sB, long sC)
{
  __shared__ bf As_h[128*PITCH], As_l[128*PITCH], Bs_h[128*PITCH], Bs_l[128*PITCH];
  long z = blockIdx.z;
  Ah += z*sA; Al += z*sA; Bh += z*sB; Bl += z*sB;
  long cbase = z*sC;
  int tid = threadIdx.x, warp = tid>>5, lane = tid&31;
  int bm = blockIdx.y*128, bn = blockIdx.x*128;
  int wm = (warp>>2)*64, wn = (warp&3)*32;
  float c[4][4][4] = {};
  // gmem->smem mapping: 512 uint4 per tile, 2 per thread
  int r0 = tid>>2, s0 = (tid&3)*8;
  int frag_r = ((lane>>3)&1)*8 + (lane&7);
  int frag_k = (lane>>4)*8;

  for(int k0=0;k0<K;k0+=32){
    const bf* pa0 = Ah + (long)(bm+r0)*K + k0 + s0;
    const bf* pa1 = Ah + (long)(bm+r0+64)*K + k0 + s0;
    const bf* qa0 = Al + (long)(bm+r0)*K + k0 + s0;
    const bf* qa1 = Al + (long)(bm+r0+64)*K + k0 + s0;
    const bf* pb0 = Bh + (long)(bn+r0)*K + k0 + s0;
    const bf* pb1 = Bh + (long)(bn+r0+64)*K + k0 + s0;
    const bf* qb0 = Bl + (long)(bn+r0)*K + k0 + s0;
    const bf* qb1 = Bl + (long)(bn+r0+64)*K + k0 + s0;
    *(uint4*)&As_h[r0*PITCH + s0]       = *(const uint4*)pa0;
    *(uint4*)&As_h[(r0+64)*PITCH + s0]  = *(const uint4*)pa1;
    *(uint4*)&As_l[r0*PITCH + s0]       = *(const uint4*)qa0;
    *(uint4*)&As_l[(r0+64)*PITCH + s0]  = *(const uint4*)qa1;
    *(uint4*)&Bs_h[r0*PITCH + s0]       = *(const uint4*)pb0;
    *(uint4*)&Bs_h[(r0+64)*PITCH + s0]  = *(const uint4*)pb1;
    *(uint4*)&Bs_l[r0*PITCH + s0]       = *(const uint4*)qb0;
    *(uint4*)&Bs_l[(r0+64)*PITCH + s0]  = *(const uint4*)qb1;
    __syncthreads();
#pragma unroll
    for(int kk=0;kk<32;kk+=16){
      uint32_t ah[4][4], al[4][4], bh2[4][2], bl2[4][2];
#pragma unroll
      for(int mi=0;mi<4;mi++){
        ldsm4(ah[mi], &As_h[(wm+mi*16+frag_r)*PITCH + kk + frag_k]);
        ldsm4(al[mi], &As_l[(wm+mi*16+frag_r)*PITCH + kk + frag_k]);
      }
#pragma unroll
      for(int p=0;p<2;p++){
        uint32_t t[4];
        ldsm4(t, &Bs_h[(wn+p*16+frag_r)*PITCH + kk + frag_k]);
        bh2[2*p][0]=t[0]; bh2[2*p][1]=t[2]; bh2[2*p+1][0]=t[1]; bh2[2*p+1][1]=t[3];
        ldsm4(t, &Bs_l[(wn+p*16+frag_r)*PITCH + kk + frag_k]);
        bl2[2*p][0]=t[0]; bl2[2*p][1]=t[2]; bl2[2*p+1][0]=t[1]; bl2[2*p+1][1]=t[3];
      }
#pragma unroll
      for(int mi=0;mi<4;mi++)
#pragma unroll
        for(int ni=0;ni<4;ni++){
          mma_bf16(c[mi][ni], ah[mi], bh2[ni]);
          mma_bf16(c[mi][ni], ah[mi], bl2[ni]);
          mma_bf16(c[mi][ni], al[mi], bh2[ni]);
        }
    }
    __syncthreads();
  }
  // epilogue
#pragma unroll
  for(int mi=0;mi<4;mi++)
#pragma unroll
  for(int ni=0;ni<4;ni++)
#pragma unroll
  for(int hh2=0;hh2<2;hh2++){
    int r = bm + wm + mi*16 + (lane>>2) + hh2*8;
    int cc = bn + wn + ni*8 + (lane&3)*2;
    float v0 = c[mi][ni][hh2*2+0], v1 = c[mi][ni][hh2*2+1];
    if(MODE==M_F32){
      *(float2*)&Cf[cbase + (long)r*N + cc] = make_float2(v0, v1);
    } else if(MODE==M_ACC){
      float2* p = (float2*)&Cf[cbase + (long)r*N + cc];
      float2 o = *p;
      *p = make_float2(o.x+v0, o.y+v1);
    } else if(MODE==M_RES){
      v0 += bias[cc]   + res[(long)r*N + cc];
      v1 += bias[cc+1] + res[(long)r*N + cc + 1];
      *(float2*)&Cf[cbase + (long)r*N + cc] = make_float2(v0, v1);
    } else if(MODE==M_GELU){
      v0 = gelu_f(v0 + bias[cc]);
      v1 = gelu_f(v1 + bias[cc+1]);
      split_write(Ch, Cl, (long)r*N + cc, v0, v1);
    } else if(MODE==M_QKV){
      v0 += bias[cc]; v1 += bias[cc+1];
      int b = r>>10, l = r&1023, hd = cc>>7, d = cc&127;
      long o = (((long)(b*Hh+hd))*Lq + l)*DKc + d;
      split_write(Ch, Cl, o, v0, v1);
    }
  }
}

// ---------------- LayerNorm -> split planes ----------------
__global__ void ln_split(const float* __restrict__ x, const float* __restrict__ g,
                         const float* __restrict__ b, bf* __restrict__ yh, bf* __restrict__ yl){
  __shared__ float red[256];
  int row = blockIdx.x;
  const float* xr = x + (size_t)row*Dd;
  float v[4]; float s = 0.f;
#pragma unroll
  for(int i=0;i<4;i++){ v[i] = xr[threadIdx.x + i*256]; s += v[i]; }
  red[threadIdx.x] = s; __syncthreads();
  for(int o=128;o>0;o>>=1){ if(threadIdx.x<o) red[threadIdx.x]+=red[threadIdx.x+o]; __syncthreads(); }
  float mean = red[0]*(1.f/Dd); __syncthreads();
  float s2 = 0.f;
#pragma unroll
  for(int i=0;i<4;i++){ float d = v[i]-mean; s2 += d*d; }
  red[threadIdx.x] = s2; __syncthreads();
  for(int o=128;o>0;o>>=1){ if(threadIdx.x<o) red[threadIdx.x]+=red[threadIdx.x+o]; __syncthreads(); }
  float inv = rsqrtf(red[0]*(1.f/Dd) + 1e-6f);
#pragma unroll
  for(int i=0;i<4;i++){
    int cidx = threadIdx.x + i*256;
    float y = g[cidx]*(v[i]-mean)*inv + b[cidx];
    bf h = __float2bfloat16(y);
    long o = (long)row*Dd + cidx;
    yh[o] = h;
    yl[o] = __float2bfloat16(y - __bfloat162float(h));
  }
}

// ---------------- weight prep ----------------
// in [rows][cols] fp32 -> out [cols][rows] hi/lo bf16
__global__ void tr_split(const float* __restrict__ in, bf* __restrict__ oh, bf* __restrict__ ol,
                         int rows, int cols, long sIn, long sOut){
  __shared__ float t[32][33];
  long z = blockIdx.z;
  in += z*sIn; oh += z*sOut; ol += z*sOut;
  int bx = blockIdx.x*32, by = blockIdx.y*32;
  int tx = threadIdx.x, ty = threadIdx.y;
#pragma unroll
  for(int i=0;i<4;i++)
    t[ty+i*8][tx] = in[(long)(by+ty+i*8)*cols + bx+tx];
  __syncthreads();
#pragma unroll
  for(int i=0;i<4;i++){
    float v = t[tx][ty+i*8];
    long o = (long)(bx+ty+i*8)*rows + by+tx;
    bf h = __float2bfloat16(v);
    oh[o] = h;
    ol[o] = __float2bfloat16(v - __bfloat162float(h));
  }
}
// flat fp32 -> hi/lo
__global__ void conv_split(const float* __restrict__ in, bf* __restrict__ oh, bf* __restrict__ ol){
  int idx = blockIdx.x*256 + threadIdx.x;
  float v = in[idx];
  bf h = __float2bfloat16(v);
  oh[idx] = h;
  ol[idx] = __float2bfloat16(v - __bfloat162float(h));
}
// transpose bf16 planes: [rows][cols] -> [cols][rows], batched
__global__ void tr_bf16(const bf* __restrict__ ih, const bf* __restrict__ il,
                        bf* __restrict__ oh, bf* __restrict__ ol,
                        int rows, int cols, long s){
  __shared__ bf th[32][33], tl[32][33];
  long z = blockIdx.z;
  ih += z*s; il += z*s; oh += z*s; ol += z*s;
  int bx = blockIdx.x*32, by = blockIdx.y*32;
  int tx = threadIdx.x, ty = threadIdx.y;
#pragma unroll
  for(int i=0;i<4;i++){
    long src = (long)(by+ty+i*8)*cols + bx+tx;
    th[ty+i*8][tx] = ih[src];
    tl[ty+i*8][tx] = il[src];
  }
  __syncthreads();
#pragma unroll
  for(int i=0;i<4;i++){
    long o = (long)(bx+ty+i*8)*rows + by+tx;
    oh[o] = th[tx][ty+i*8];
    ol[o] = tl[tx][ty+i*8];
  }
}

// ---------------- softmax (gather + scale + ap + mask) -> attn hi/lo ----------------
__global__ void softmax_kernel(const float* __restrict__ scores, const float* __restrict__ qr,
                               const int* __restrict__ pm, const int* __restrict__ mask,
                               const float* __restrict__ ap,
                               bf* __restrict__ outh, bf* __restrict__ outl){
  __shared__ float red[256];
  int bh = blockIdx.y;
  int b  = bh / Hh;
  int i  = blockIdx.x;
  const float* srow = scores + ((size_t)bh*Lq + i)*Lq;
  const float* qrow = qr + ((size_t)bh*Lq + i)*Pp;
  const int*   prow = pm + ((size_t)b*Lq + i)*Lq;
  const int*   mrow = mask + ((size_t)b*Lq + i)*Lq;
  const float* arow = ap + ((size_t)bh*Lq + i)*Lq;
  const float scale = 0.08838834764831845f;
  float v[4]; float mx = -3.0e38f;
#pragma unroll
  for(int k=0;k<4;k++){
    int j = threadIdx.x + k*256;
    float val;
    if(mrow[j]==0) val = -1e9f;
    else           val = (srow[j] + qrow[prow[j]])*scale + arow[j];
    v[k] = val; mx = fmaxf(mx, val);
  }
  red[threadIdx.x] = mx; __syncthreads();
  for(int o=128;o>0;o>>=1){ if(threadIdx.x<o) red[threadIdx.x]=fmaxf(red[threadIdx.x],red[threadIdx.x+o]); __syncthreads(); }
  mx = red[0]; __syncthreads();
  float s = 0.f;
#pragma unroll
  for(int k=0;k<4;k++){ v[k] = expf(v[k]-mx); s += v[k]; }
  red[threadIdx.x] = s; __syncthreads();
  for(int o=128;o>0;o>>=1){ if(threadIdx.x<o) red[threadIdx.x]+=red[threadIdx.x+o]; __syncthreads(); }
  float inv = 1.f/red[0];
  long obase = ((size_t)bh*Lq + i)*Lq;
#pragma unroll
  for(int k=0;k<4;k++){
    int j = threadIdx.x + k*256;
    float a = v[k]*inv;
    bf h = __float2bfloat16(a);
    outh[obase + j] = h;
    outl[obase + j] = __float2bfloat16(a - __bfloat162float(h));
  }
}

// ---------------- scatter attn into path buckets -> hi/lo ----------------
__global__ void scatter_kernel(const bf* __restrict__ ah, const bf* __restrict__ al,
                               const int* __restrict__ pm,
                               bf* __restrict__ ph, bf* __restrict__ pl){
  __shared__ float sp[Pp];
  int bh = blockIdx.y;
  int b  = bh / Hh;
  int i  = blockIdx.x;
#pragma unroll
  for(int k=0;k<4;k++) sp[threadIdx.x + k*256] = 0.f;
  __syncthreads();
  long abase = ((size_t)bh*Lq + i)*Lq;
  const int* prow = pm + ((size_t)b*Lq + i)*Lq;
#pragma unroll
  for(int k=0;k<4;k++){
    int j = threadIdx.x + k*256;
    float a = __bfloat162float(ah[abase+j]) + __bfloat162float(al[abase+j]);
    atomicAdd(&sp[prow[j]], a);
  }
  __syncthreads();
  long obase = ((size_t)bh*Lq + i)*Pp;
#pragma unroll
  for(int k=0;k<4;k++){
    int cidx = threadIdx.x + k*256;
    float v = sp[cidx];
    bf h = __float2bfloat16(v);
    ph[obase+cidx] = h;
    pl[obase+cidx] = __float2bfloat16(v - __bfloat162float(h));
  }
}

// ---------------- merge heads fp32 [B,H,L,DK] -> split [B,L,D] ----------------
__global__ void merge_split(const float* __restrict__ in, bf* __restrict__ oh, bf* __restrict__ ol){
  int idx = blockIdx.x*256 + threadIdx.x;
  float v = in[idx];
  int d = idx & 127;
  int l = (idx >> 7) & 1023;
  int hd = (idx >> 17) & 7;
  int b = idx >> 20;
  long o = ((long)(b*Lq + l))*Dd + hd*DKc + d;
  bf h = __float2bfloat16(v);
  oh[o] = h;
  ol[o] = __float2bfloat16(v - __bfloat162float(h));
}

// ---------------- launch ----------------
extern "C" void kernel_launch(void* const* d_in, const int* in_sizes, int n_in,
                              void* d_out, int out_size){
  const float* content = (const float*)d_in[0];
  const int*   mask    = (const int*)  d_in[1];
  const float* r_k     = (const float*)d_in[2];
  const float* r_v     = (const float*)d_in[3];
  const int*   path_map= (const int*)  d_in[4];
  const float* ap      = (const float*)d_in[5];
  const float* wq = (const float*)d_in[6];  const float* bq = (const float*)d_in[7];
  const float* wk = (const float*)d_in[8];  const float* bk = (const float*)d_in[9];
  const float* wv = (const float*)d_in[10]; const float* bv = (const float*)d_in[11];
  const float* wo = (const float*)d_in[12]; const float* bo = (const float*)d_in[13];
  const float* ln1g = (const float*)d_in[14]; const float* ln1b = (const float*)d_in[15];
  const float* ln2g = (const float*)d_in[16]; const float* ln2b = (const float*)d_in[17];
  const float* w1 = (const float*)d_in[18]; const float* b1 = (const float*)d_in[19];
  const float* w2 = (const float*)d_in[20]; const float* b2 = (const float*)d_in[21];
  float* out = (float*)d_out;

  bf *xnh,*xnl,*qh,*ql,*kh,*kl,*vh,*vl,*vth,*vtl,*hh,*hl,*ath,*atl,*pth,*ptl;
  bf *wqh,*wql,*wkh,*wkl,*wvh,*wvl,*woh,*wol,*w1h,*w1l,*w2h,*w2l,*rkh,*rkl,*rvh,*rvl;
  float *sc,*qr,*aout,*x;
  cudaGetSymbolAddress((void**)&xnh, g_xn_h); cudaGetSymbolAddress((void**)&xnl, g_xn_l);
  cudaGetSymbolAddress((void**)&qh, g_q_h);   cudaGetSymbolAddress((void**)&ql, g_q_l);
  cudaGetSymbolAddress((void**)&kh, g_k_h);   cudaGetSymbolAddress((void**)&kl, g_k_l);
  cudaGetSymbolAddress((void**)&vh, g_v_h);   cudaGetSymbolAddress((void**)&vl, g_v_l);
  cudaGetSymbolAddress((void**)&vth, g_vt_h); cudaGetSymbolAddress((void**)&vtl, g_vt_l);
  cudaGetSymbolAddress((void**)&hh, g_h_h);   cudaGetSymbolAddress((void**)&hl, g_h_l);
  cudaGetSymbolAddress((void**)&ath, g_attn_h); cudaGetSymbolAddress((void**)&atl, g_attn_l);
  cudaGetSymbolAddress((void**)&pth, g_path_h); cudaGetSymbolAddress((void**)&ptl, g_path_l);
  cudaGetSymbolAddress((void**)&wqh, g_wqt_h); cudaGetSymbolAddress((void**)&wql, g_wqt_l);
  cudaGetSymbolAddress((void**)&wkh, g_wkt_h); cudaGetSymbolAddress((void**)&wkl, g_wkt_l);
  cudaGetSymbolAddress((void**)&wvh, g_wvt_h); cudaGetSymbolAddress((void**)&wvl, g_wvt_l);
  cudaGetSymbolAddress((void**)&woh, g_wot_h); cudaGetSymbolAddress((void**)&wol, g_wot_l);
  cudaGetSymbolAddress((void**)&w1h, g_w1t_h); cudaGetSymbolAddress((void**)&w1l, g_w1t_l);
  cudaGetSymbolAddress((void**)&w2h, g_w2t_h); cudaGetSymbolAddress((void**)&w2l, g_w2t_l);
  cudaGetSymbolAddress((void**)&rkh, g_rk_h);  cudaGetSymbolAddress((void**)&rkl, g_rk_l);
  cudaGetSymbolAddress((void**)&rvh, g_rvt_h); cudaGetSymbolAddress((void**)&rvl, g_rvt_l);
  cudaGetSymbolAddress((void**)&sc, g_scores);
  cudaGetSymbolAddress((void**)&qr, g_qr);
  cudaGetSymbolAddress((void**)&aout, g_aout);
  cudaGetSymbolAddress((void**)&x, g_x);

  dim3 tb(32,8);
  // weight prep: W[K][N] -> Wt[N][K] hi/lo
  tr_split<<<dim3(Dd/32, Dd/32, 1), tb>>>(wq, wqh, wql, Dd, Dd, 0, 0);
  tr_split<<<dim3(Dd/32, Dd/32, 1), tb>>>(wk, wkh, wkl, Dd, Dd, 0, 0);
  tr_split<<<dim3(Dd/32, Dd/32, 1), tb>>>(wv, wvh, wvl, Dd, Dd, 0, 0);
  tr_split<<<dim3(Dd/32, Dd/32, 1), tb>>>(wo, woh, wol, Dd, Dd, 0, 0);
  tr_split<<<dim3(Ff/32, Dd/32, 1), tb>>>(w1, w1h, w1l, Dd, Ff, 0, 0);
  tr_split<<<dim3(Dd/32, Ff/32, 1), tb>>>(w2, w2h, w2l, Ff, Dd, 0, 0);
  conv_split<<<(Bb*Hh*Pp*DKc)/256, 256>>>(r_k, rkh, rkl);
  tr_split<<<dim3(DKc/32, Pp/32, Bb*Hh), tb>>>(r_v, rvh, rvl, Pp, DKc, (long)Pp*DKc, (long)Pp*DKc);

  // 1) LN1 -> xn hi/lo
  ln_split<<<Bb*Lq, 256>>>(content, ln1g, ln1b, xnh, xnl);

  // 2) QKV
  dim3 gqkv(Dd/128, (Bb*Lq)/128, 1);
  hgemm<M_QKV><<<gqkv,256>>>(xnh,xnl, wqh,wql, bq, nullptr, nullptr, qh,ql, Bb*Lq, Dd, Dd, 0,0,0);
  hgemm<M_QKV><<<gqkv,256>>>(xnh,xnl, wkh,wkl, bk, nullptr, nullptr, kh,kl, Bb*Lq, Dd, Dd, 0,0,0);
  hgemm<M_QKV><<<gqkv,256>>>(xnh,xnl, wvh,wvl, bv, nullptr, nullptr, vh,vl, Bb*Lq, Dd, Dd, 0,0,0);

  // v -> vt [bh][DK][L]
  tr_bf16<<<dim3(DKc/32, Lq/32, Bb*Hh), tb>>>(vh, vl, vth, vtl, Lq, DKc, (long)Lq*DKc);

  // 3) scores = q@k^T ; qr = q@rk^T (batched over B*H)
  long sQK = (long)Lq*DKc;
  hgemm<M_F32><<<dim3(Lq/128, Lq/128, Bb*Hh),256>>>(qh,ql, kh,kl, nullptr, nullptr, sc, nullptr,nullptr,
                                                    Lq, Lq, DKc, sQK, sQK, (long)Lq*Lq);
  hgemm<M_F32><<<dim3(Pp/128, Lq/128, Bb*Hh),256>>>(qh,ql, rkh,rkl, nullptr, nullptr, qr, nullptr,nullptr,
                                                    Lq, Pp, DKc, sQK, (long)Pp*DKc, (long)Lq*Pp);
  // 4) softmax
  softmax_kernel<<<dim3(Lq, Bb*Hh),256>>>(sc, qr, path_map, mask, ap, ath, atl);
  // 5) scatter
  scatter_kernel<<<dim3(Lq, Bb*Hh),256>>>(ath, atl, path_map, pth, ptl);
  // 6) aout = attn@v ; aout += path@r_v
  hgemm<M_F32><<<dim3(DKc/128, Lq/128, Bb*Hh),256>>>(ath,atl, vth,vtl, nullptr, nullptr, aout, nullptr,nullptr,
                                                     Lq, DKc, Lq, (long)Lq*Lq, (long)DKc*Lq, (long)Lq*DKc);
  hgemm<M_ACC><<<dim3(DKc/128, Lq/128, Bb*Hh),256>>>(pth,ptl, rvh,rvl, nullptr, nullptr, aout, nullptr,nullptr,
                                                     Lq, DKc, Pp, (long)Lq*Pp, (long)DKc*Pp, (long)Lq*DKc);
  // 7) merge heads -> xn hi/lo
  merge_split<<<(Bb*Hh*Lq*DKc)/256, 256>>>(aout, xnh, xnl);
  // 8) x = merged@wo + bo + content
  hgemm<M_RES><<<dim3(Dd/128,(Bb*Lq)/128,1),256>>>(xnh,xnl, woh,wol, bo, content, x, nullptr,nullptr,
                                                   Bb*Lq, Dd, Dd, 0,0,0);
  // 9) LN2
  ln_split<<<Bb*Lq, 256>>>(x, ln2g, ln2b, xnh, xnl);
  // 10) h = gelu(xn@w1 + b1) hi/lo
  hgemm<M_GELU><<<dim3(Ff/128,(Bb*Lq)/128,1),256>>>(xnh,xnl, w1h,w1l, b1, nullptr, nullptr, hh,hl,
                                                    Bb*Lq, Ff, Dd, 0,0,0);
  // 11) out = h@w2 + b2 + x
  hgemm<M_RES><<<dim3(Dd/128,(Bb*Lq)/128,1),256>>>(hh,hl, w2h,w2l, b2, x, out, nullptr,nullptr,
                                                   Bb*Lq, Dd, Ff, 0,0,0);
}

// round 5
// speedup vs baseline: 2.1799x; 1.0155x over previous
#include <cuda_runtime.h>
#include <cuda_bf16.h>
#include <cstdint>
#include <math.h>

typedef __nv_bfloat16 bf;

#define Bb 4
#define Lq 1024
#define Dd 1024
#define Hh 8
#define Pp 1024
#define Ff 4096
#define DKc 128

// ---------------- scratch ----------------
__device__ bf g_xn_h[Bb*Lq*Dd], g_xn_l[Bb*Lq*Dd];
__device__ bf g_q_h[Bb*Hh*Lq*DKc], g_q_l[Bb*Hh*Lq*DKc];
__device__ bf g_k_h[Bb*Hh*Lq*DKc], g_k_l[Bb*Hh*Lq*DKc];
__device__ bf g_v_h[Bb*Hh*Lq*DKc], g_v_l[Bb*Hh*Lq*DKc];
__device__ bf g_vt_h[Bb*Hh*Lq*DKc], g_vt_l[Bb*Hh*Lq*DKc];
__device__ bf g_h_h[Bb*Lq*Ff], g_h_l[Bb*Lq*Ff];
__device__ bf g_attn_h[(size_t)Bb*Hh*Lq*Lq], g_attn_l[(size_t)Bb*Hh*Lq*Lq];
__device__ bf g_path_h[(size_t)Bb*Hh*Lq*Pp], g_path_l[(size_t)Bb*Hh*Lq*Pp];
__device__ bf g_wqt_h[Dd*Dd], g_wqt_l[Dd*Dd];
__device__ bf g_wkt_h[Dd*Dd], g_wkt_l[Dd*Dd];
__device__ bf g_wvt_h[Dd*Dd], g_wvt_l[Dd*Dd];
__device__ bf g_wot_h[Dd*Dd], g_wot_l[Dd*Dd];
__device__ bf g_w1t_h[Dd*Ff], g_w1t_l[Dd*Ff];
__device__ bf g_w2t_h[Dd*Ff], g_w2t_l[Dd*Ff];
__device__ bf g_rk_h[Bb*Hh*Pp*DKc], g_rk_l[Bb*Hh*Pp*DKc];
__device__ bf g_rvt_h[Bb*Hh*Pp*DKc], g_rvt_l[Bb*Hh*Pp*DKc];
__device__ float g_scores[(size_t)Bb*Hh*Lq*Lq];
__device__ float g_qr[(size_t)Bb*Hh*Lq*Pp];
__device__ float g_aout[Bb*Hh*Lq*DKc];
__device__ float g_x[Bb*Lq*Dd];

// ---------------- helpers ----------------
__device__ __forceinline__ void ldsm4(uint32_t r[4], const bf* p){
  uint32_t a = (uint32_t)__cvta_generic_to_shared(p);
  asm volatile("ldmatrix.sync.aligned.m8n8.x4.shared.b16 {%0,%1,%2,%3},[%4];"
    :"=r"(r[0]),"=r"(r[1]),"=r"(r[2]),"=r"(r[3]):"r"(a));
}
__device__ __forceinline__ void mma_bf16(float c[4], const uint32_t a[4], const uint32_t b[2]){
  asm volatile("mma.sync.aligned.m16n8k16.row.col.f32.bf16.bf16.f32 "
    "{%0,%1,%2,%3},{%4,%5,%6,%7},{%8,%9},{%0,%1,%2,%3};"
    :"+f"(c[0]),"+f"(c[1]),"+f"(c[2]),"+f"(c[3])
    :"r"(a[0]),"r"(a[1]),"r"(a[2]),"r"(a[3]),"r"(b[0]),"r"(b[1]));
}
__device__ __forceinline__ void cpa16(bf* dst, const bf* src){
  uint32_t d = (uint32_t)__cvta_generic_to_shared(dst);
  asm volatile("cp.async.cg.shared.global [%0],[%1],16;"::"r"(d),"l"(src));
}
__device__ __forceinline__ void cpa_commit(){ asm volatile("cp.async.commit_group;"); }
template<int N> __device__ __forceinline__ void cpa_wait(){ asm volatile("cp.async.wait_group %0;"::"n"(N)); }

__device__ __forceinline__ void split_write(bf* H, bf* L, long o, float v0, float v1){
  bf h0 = __float2bfloat16(v0), h1 = __float2bfloat16(v1);
  bf l0 = __float2bfloat16(v0 - __bfloat162float(h0));
  bf l1 = __float2bfloat16(v1 - __bfloat162float(h1));
  __nv_bfloat162 hh; hh.x = h0; hh.y = h1;
  __nv_bfloat162 ll; ll.x = l0; ll.y = l1;
  *(__nv_bfloat162*)&H[o] = hh;
  *(__nv_bfloat162*)&L[o] = ll;
}
__device__ __forceinline__ float gelu_f(float u){
  return 0.5f*u*(1.f + tanhf(0.7978845608028654f*(u + 0.044715f*u*u*u)));
}

// ---------------- split-bf16 tensor-core GEMM, 2-stage cp.async pipeline ----------------
// A[M][K] hi/lo row-major, B[N][K] hi/lo row-major (pre-transposed). 128x128 tile, 8 warps.
#define M_F32   0
#define M_ACC   1
#define M_QKV   2
#define M_GELU  3
#define M_RES   4
#define M_SCORE 5

#define PITCH 40
#define PLANE (128*PITCH)
#define STAGE (4*PLANE)
#define SMEM_BYTES (2*STAGE*2)

template<int MODE>
__global__ __launch_bounds__(256)
void hgemm(const bf* __restrict__ Ah, const bf* __restrict__ Al,
           const bf* __restrict__ Bh, const bf* __restrict__ Bl,
           const float* __restrict__ bias, const float* __restrict__ res,
           const int* __restrict__ pm, const int* __restrict__ msk,
           float* __restrict__ Cf, bf* __restrict__ Ch, bf* __restrict__ Cl,
           int M, int N, int K, long sA, long sB, long sC)
{
  extern __shared__ bf sm[];
  long z = blockIdx.z;
  Ah += z*sA; Al += z*sA; Bh += z*sB; Bl += z*sB;
  long cbase = z*sC;
  int tid = threadIdx.x, warp = tid>>5, lane = tid&31;
  int bm = blockIdx.y*128, bn = blockIdx.x*128;
  int wm = (warp>>2)*64, wn = (warp&3)*32;
  float c[4][4][4] = {};
  int r0 = tid>>2, s0 = (tid&3)*8;
  int frag_r = ((lane>>3)&1)*8 + (lane&7);
  int frag_k = (lane>>4)*8;

  const bf* pa0 = Ah + (long)(bm+r0)*K + s0;
  const bf* pa1 = Ah + (long)(bm+r0+64)*K + s0;
  const bf* qa0 = Al + (long)(bm+r0)*K + s0;
  const bf* qa1 = Al + (long)(bm+r0+64)*K + s0;
  const bf* pb0 = Bh + (long)(bn+r0)*K + s0;
  const bf* pb1 = Bh + (long)(bn+r0+64)*K + s0;
  const bf* qb0 = Bl + (long)(bn+r0)*K + s0;
  const bf* qb1 = Bl + (long)(bn+r0+64)*K + s0;

  int T = K >> 5;
  // prologue: issue tile 0 into stage 0
  {
    bf* st = sm;
    cpa16(&st[0*PLANE + r0*PITCH + s0],      pa0);
    cpa16(&st[0*PLANE + (r0+64)*PITCH + s0], pa1);
    cpa16(&st[1*PLANE + r0*PITCH + s0],      qa0);
    cpa16(&st[1*PLANE + (r0+64)*PITCH + s0], qa1);
    cpa16(&st[2*PLANE + r0*PITCH + s0],      pb0);
    cpa16(&st[2*PLANE + (r0+64)*PITCH + s0], pb1);
    cpa16(&st[3*PLANE + r0*PITCH + s0],      qb0);
    cpa16(&st[3*PLANE + (r0+64)*PITCH + s0], qb1);
    cpa_commit();
  }
  for(int t=0;t<T;t++){
    if(t+1<T){
      int k0 = (t+1)<<5;
      bf* st = sm + ((t+1)&1)*STAGE;
      cpa16(&st[0*PLANE + r0*PITCH + s0],      pa0 + k0);
      cpa16(&st[0*PLANE + (r0+64)*PITCH + s0], pa1 + k0);
      cpa16(&st[1*PLANE + r0*PITCH + s0],      qa0 + k0);
      cpa16(&st[1*PLANE + (r0+64)*PITCH + s0], qa1 + k0);
      cpa16(&st[2*PLANE + r0*PITCH + s0],      pb0 + k0);
      cpa16(&st[2*PLANE + (r0+64)*PITCH + s0], pb1 + k0);
      cpa16(&st[3*PLANE + r0*PITCH + s0],      qb0 + k0);
      cpa16(&st[3*PLANE + (r0+64)*PITCH + s0], qb1 + k0);
      cpa_commit();
      cpa_wait<1>();
    } else {
      cpa_wait<0>();
    }
    __syncthreads();
    bf* st = sm + (t&1)*STAGE;
    bf* As_h = st;           bf* As_l = st + PLANE;
    bf* Bs_h = st + 2*PLANE; bf* Bs_l = st + 3*PLANE;
#pragma unroll
    for(int kk=0;kk<32;kk+=16){
      uint32_t ah[4][4], al[4][4], bh2[4][2], bl2[4][2];
#pragma unroll
      for(int mi=0;mi<4;mi++){
        ldsm4(ah[mi], &As_h[(wm+mi*16+frag_r)*PITCH + kk + frag_k]);
        ldsm4(al[mi], &As_l[(wm+mi*16+frag_r)*PITCH + kk + frag_k]);
      }
#pragma unroll
      for(int p=0;p<2;p++){
        uint32_t t4[4];
        ldsm4(t4, &Bs_h[(wn+p*16+frag_r)*PITCH + kk + frag_k]);
        bh2[2*p][0]=t4[0]; bh2[2*p][1]=t4[2]; bh2[2*p+1][0]=t4[1]; bh2[2*p+1][1]=t4[3];
        ldsm4(t4, &Bs_l[(wn+p*16+frag_r)*PITCH + kk + frag_k]);
        bl2[2*p][0]=t4[0]; bl2[2*p][1]=t4[2]; bl2[2*p+1][0]=t4[1]; bl2[2*p+1][1]=t4[3];
      }
#pragma unroll
      for(int mi=0;mi<4;mi++)
#pragma unroll
        for(int ni=0;ni<4;ni++){
          mma_bf16(c[mi][ni], ah[mi], bh2[ni]);
          mma_bf16(c[mi][ni], ah[mi], bl2[ni]);
          mma_bf16(c[mi][ni], al[mi], bh2[ni]);
        }
    }
    __syncthreads();
  }
  // epilogue
#pragma unroll
  for(int mi=0;mi<4;mi++)
#pragma unroll
  for(int ni=0;ni<4;ni++)
#pragma unroll
  for(int hh2=0;hh2<2;hh2++){
    int r = bm + wm + mi*16 + (lane>>2) + hh2*8;
    int cc = bn + wn + ni*8 + (lane&3)*2;
    float v0 = c[mi][ni][hh2*2+0], v1 = c[mi][ni][hh2*2+1];
    if(MODE==M_F32){
      *(float2*)&Cf[cbase + (long)r*N + cc] = make_float2(v0, v1);
    } else if(MODE==M_ACC){
      float2* p = (float2*)&Cf[cbase + (long)r*N + cc];
      float2 o = *p;
      *p = make_float2(o.x+v0, o.y+v1);
    } else if(MODE==M_RES){
      v0 += bias[cc]   + res[(long)r*N + cc];
      v1 += bias[cc+1] + res[(long)r*N + cc + 1];
      *(float2*)&Cf[cbase + (long)r*N + cc] = make_float2(v0, v1);
    } else if(MODE==M_GELU){
      v0 = gelu_f(v0 + bias[cc]);
      v1 = gelu_f(v1 + bias[cc+1]);
      split_write(Ch, Cl, (long)r*N + cc, v0, v1);
    } else if(MODE==M_QKV){
      v0 += bias[cc]; v1 += bias[cc+1];
      int b = r>>10, l = r&1023, hd = cc>>7, d = cc&127;
      long o = (((long)(b*Hh+hd))*Lq + l)*DKc + d;
      split_write(Ch, Cl, o, v0, v1);
    } else if(MODE==M_SCORE){
      // bias = qr [z][Lq][Pp], res = ap [z][Lq][Lq], pm/msk per-batch [b][Lq][Lq]
      const float scale = 0.08838834764831845f;
      long b = z >> 3;
      long rowq = z*((long)Lq*Pp) + (long)r*Pp;
      long rowm = b*((long)Lq*Lq) + (long)r*Lq;
      long rowa = z*((long)Lq*Lq) + (long)r*Lq;
      int p0 = pm[rowm + cc], p1 = pm[rowm + cc + 1];
      int m0 = msk[rowm + cc], m1 = msk[rowm + cc + 1];
      float s0v = (v0 + bias[rowq + p0])*scale + res[rowa + cc];
      float s1v = (v1 + bias[rowq + p1])*scale + res[rowa + cc + 1];
      if(m0==0) s0v = -1e9f;
      if(m1==0) s1v = -1e9f;
      *(float2*)&Cf[cbase + (long)r*N + cc] = make_float2(s0v, s1v);
    }
  }
}

// ---------------- LayerNorm -> split planes ----------------
__global__ void ln_split(const float* __restrict__ x, const float* __restrict__ g,
                         const float* __restrict__ b, bf* __restrict__ yh, bf* __restrict__ yl){
  __shared__ float red[256];
  int row = blockIdx.x;
  const float* xr = x + (size_t)row*Dd;
  float v[4]; float s = 0.f;
#pragma unroll
  for(int i=0;i<4;i++){ v[i] = xr[threadIdx.x + i*256]; s += v[i]; }
  red[threadIdx.x] = s; __syncthreads();
  for(int o=128;o>0;o>>=1){ if(threadIdx.x<o) red[threadIdx.x]+=red[threadIdx.x+o]; __syncthreads(); }
  float mean = red[0]*(1.f/Dd); __syncthreads();
  float s2 = 0.f;
#pragma unroll
  for(int i=0;i<4;i++){ float d = v[i]-mean; s2 += d*d; }
  red[threadIdx.x] = s2; __syncthreads();
  for(int o=128;o>0;o>>=1){ if(threadIdx.x<o) red[threadIdx.x]+=red[threadIdx.x+o]; __syncthreads(); }
  float inv = rsqrtf(red[0]*(1.f/Dd) + 1e-6f);
#pragma unroll
  for(int i=0;i<4;i++){
    int cidx = threadIdx.x + i*256;
    float y = g[cidx]*(v[i]-mean)*inv + b[cidx];
    bf h = __float2bfloat16(y);
    long o = (long)row*Dd + cidx;
    yh[o] = h;
    yl[o] = __float2bfloat16(y - __bfloat162float(h));
  }
}

// ---------------- weight prep ----------------
__global__ void tr_split(const float* __restrict__ in, bf* __restrict__ oh, bf* __restrict__ ol,
                         int rows, int cols, long sIn, long sOut){
  __shared__ float t[32][33];
  long z = blockIdx.z;
  in += z*sIn; oh += z*sOut; ol += z*sOut;
  int bx = blockIdx.x*32, by = blockIdx.y*32;
  int tx = threadIdx.x, ty = threadIdx.y;
#pragma unroll
  for(int i=0;i<4;i++)
    t[ty+i*8][tx] = in[(long)(by+ty+i*8)*cols + bx+tx];
  __syncthreads();
#pragma unroll
  for(int i=0;i<4;i++){
    float v = t[tx][ty+i*8];
    long o = (long)(bx+ty+i*8)*rows + by+tx;
    bf h = __float2bfloat16(v);
    oh[o] = h;
    ol[o] = __float2bfloat16(v - __bfloat162float(h));
  }
}
__global__ void conv_split(const float* __restrict__ in, bf* __restrict__ oh, bf* __restrict__ ol){
  int idx = blockIdx.x*256 + threadIdx.x;
  float v = in[idx];
  bf h = __float2bfloat16(v);
  oh[idx] = h;
  ol[idx] = __float2bfloat16(v - __bfloat162float(h));
}
__global__ void tr_bf16(const bf* __restrict__ ih, const bf* __restrict__ il,
                        bf* __restrict__ oh, bf* __restrict__ ol,
                        int rows, int cols, long s){
  __shared__ bf th[32][33], tl[32][33];
  long z = blockIdx.z;
  ih += z*s; il += z*s; oh += z*s; ol += z*s;
  int bx = blockIdx.x*32, by = blockIdx.y*32;
  int tx = threadIdx.x, ty = threadIdx.y;
#pragma unroll
  for(int i=0;i<4;i++){
    long src = (long)(by+ty+i*8)*cols + bx+tx;
    th[ty+i*8][tx] = ih[src];
    tl[ty+i*8][tx] = il[src];
  }
  __syncthreads();
#pragma unroll
  for(int i=0;i<4;i++){
    long o = (long)(bx+ty+i*8)*rows + by+tx;
    oh[o] = th[tx][ty+i*8];
    ol[o] = tl[tx][ty+i*8];
  }
}

// ---------------- fused softmax + scatter ----------------
// scores already have gather+scale+ap+mask applied (M_SCORE epilogue).
__global__ void softmax_scatter(const float* __restrict__ scores, const int* __restrict__ pm,
                                bf* __restrict__ outh, bf* __restrict__ outl,
                                bf* __restrict__ ph, bf* __restrict__ pl){
  __shared__ float red[256];
  __shared__ float sp[Pp];
  int bh = blockIdx.y;
  int b  = bh >> 3;
  int i  = blockIdx.x;
  const float* srow = scores + ((size_t)bh*Lq + i)*Lq;
  const int*   prow = pm + ((size_t)b*Lq + i)*Lq;
#pragma unroll
  for(int k=0;k<4;k++) sp[threadIdx.x + k*256] = 0.f;
  float v[4]; float mx = -3.0e38f;
#pragma unroll
  for(int k=0;k<4;k++){
    v[k] = srow[threadIdx.x + k*256];
    mx = fmaxf(mx, v[k]);
  }
  red[threadIdx.x] = mx; __syncthreads();
  for(int o=128;o>0;o>>=1){ if(threadIdx.x<o) red[threadIdx.x]=fmaxf(red[threadIdx.x],red[threadIdx.x+o]); __syncthreads(); }
  mx = red[0]; __syncthreads();
  float s = 0.f;
#pragma unroll
  for(int k=0;k<4;k++){ v[k] = expf(v[k]-mx); s += v[k]; }
  red[threadIdx.x] = s; __syncthreads();
  for(int o=128;o>0;o>>=1){ if(threadIdx.x<o) red[threadIdx.x]+=red[threadIdx.x+o]; __syncthreads(); }
  float inv = 1.f/red[0];
  long obase = ((size_t)bh*Lq + i)*Lq;
#pragma unroll
  for(int k=0;k<4;k++){
    int j = threadIdx.x + k*256;
    float a = v[k]*inv;
    bf h = __float2bfloat16(a);
    outh[obase + j] = h;
    outl[obase + j] = __float2bfloat16(a - __bfloat162float(h));
    atomicAdd(&sp[prow[j]], a);
  }
  __syncthreads();
  long pbase = ((size_t)bh*Lq + i)*Pp;
#pragma unroll
  for(int k=0;k<4;k++){
    int cidx = threadIdx.x + k*256;
    float pv = sp[cidx];
    bf h = __float2bfloat16(pv);
    ph[pbase+cidx] = h;
    pl[pbase+cidx] = __float2bfloat16(pv - __bfloat162float(h));
  }
}

// ---------------- merge heads fp32 [B,H,L,DK] -> split [B,L,D] ----------------
__global__ void merge_split(const float* __restrict__ in, bf* __restrict__ oh, bf* __restrict__ ol){
  int idx = blockIdx.x*256 + threadIdx.x;
  float v = in[idx];
  int d = idx & 127;
  int l = (idx >> 7) & 1023;
  int hd = (idx >> 17) & 7;
  int b = idx >> 20;
  long o = ((long)(b*Lq + l))*Dd + hd*DKc + d;
  bf h = __float2bfloat16(v);
  oh[o] = h;
  ol[o] = __float2bfloat16(v - __bfloat162float(h));
}

// ---------------- launch ----------------
extern "C" void kernel_launch(void* const* d_in, const int* in_sizes, int n_in,
                              void* d_out, int out_size){
  const float* content = (const float*)d_in[0];
  const int*   mask    = (const int*)  d_in[1];
  const float* r_k     = (const float*)d_in[2];
  const float* r_v     = (const float*)d_in[3];
  const int*   path_map= (const int*)  d_in[4];
  const float* ap      = (const float*)d_in[5];
  const float* wq = (const float*)d_in[6];  const float* bq = (const float*)d_in[7];
  const float* wk = (const float*)d_in[8];  const float* bk = (const float*)d_in[9];
  const float* wv = (const float*)d_in[10]; const float* bv = (const float*)d_in[11];
  const float* wo = (const float*)d_in[12]; const float* bo = (const float*)d_in[13];
  const float* ln1g = (const float*)d_in[14]; const float* ln1b = (const float*)d_in[15];
  const float* ln2g = (const float*)d_in[16]; const float* ln2b = (const float*)d_in[17];
  const float* w1 = (const float*)d_in[18]; const float* b1 = (const float*)d_in[19];
  const float* w2 = (const float*)d_in[20]; const float* b2 = (const float*)d_in[21];
  float* out = (float*)d_out;

  bf *xnh,*xnl,*qh,*ql,*kh,*kl,*vh,*vl,*vth,*vtl,*hh,*hl,*ath,*atl,*pth,*ptl;
  bf *wqh,*wql,*wkh,*wkl,*wvh,*wvl,*woh,*wol,*w1h,*w1l,*w2h,*w2l,*rkh,*rkl,*rvh,*rvl;
  float *sc,*qr,*aout,*x;
  cudaGetSymbolAddress((void**)&xnh, g_xn_h); cudaGetSymbolAddress((void**)&xnl, g_xn_l);
  cudaGetSymbolAddress((void**)&qh, g_q_h);   cudaGetSymbolAddress((void**)&ql, g_q_l);
  cudaGetSymbolAddress((void**)&kh, g_k_h);   cudaGetSymbolAddress((void**)&kl, g_k_l);
  cudaGetSymbolAddress((void**)&vh, g_v_h);   cudaGetSymbolAddress((void**)&vl, g_v_l);
  cudaGetSymbolAddress((void**)&vth, g_vt_h); cudaGetSymbolAddress((void**)&vtl, g_vt_l);
  cudaGetSymbolAddress((void**)&hh, g_h_h);   cudaGetSymbolAddress((void**)&hl, g_h_l);
  cudaGetSymbolAddress((void**)&ath, g_attn_h); cudaGetSymbolAddress((void**)&atl, g_attn_l);
  cudaGetSymbolAddress((void**)&pth, g_path_h); cudaGetSymbolAddress((void**)&ptl, g_path_l);
  cudaGetSymbolAddress((void**)&wqh, g_wqt_h); cudaGetSymbolAddress((void**)&wql, g_wqt_l);
  cudaGetSymbolAddress((void**)&wkh, g_wkt_h); cudaGetSymbolAddress((void**)&wkl, g_wkt_l);
  cudaGetSymbolAddress((void**)&wvh, g_wvt_h); cudaGetSymbolAddress((void**)&wvl, g_wvt_l);
  cudaGetSymbolAddress((void**)&woh, g_wot_h); cudaGetSymbolAddress((void**)&wol, g_wot_l);
  cudaGetSymbolAddress((void**)&w1h, g_w1t_h); cudaGetSymbolAddress((void**)&w1l, g_w1t_l);
  cudaGetSymbolAddress((void**)&w2h, g_w2t_h); cudaGetSymbolAddress((void**)&w2l, g_w2t_l);
  cudaGetSymbolAddress((void**)&rkh, g_rk_h);  cudaGetSymbolAddress((void**)&rkl, g_rk_l);
  cudaGetSymbolAddress((void**)&rvh, g_rvt_h); cudaGetSymbolAddress((void**)&rvl, g_rvt_l);
  cudaGetSymbolAddress((void**)&sc, g_scores);
  cudaGetSymbolAddress((void**)&qr, g_qr);
  cudaGetSymbolAddress((void**)&aout, g_aout);
  cudaGetSymbolAddress((void**)&x, g_x);

  // allow 80KB dynamic smem on all hgemm instantiations
  cudaFuncSetAttribute(hgemm<M_F32>,   cudaFuncAttributeMaxDynamicSharedMemorySize, SMEM_BYTES);
  cudaFuncSetAttribute(hgemm<M_ACC>,   cudaFuncAttributeMaxDynamicSharedMemorySize, SMEM_BYTES);
  cudaFuncSetAttribute(hgemm<M_QKV>,   cudaFuncAttributeMaxDynamicSharedMemorySize, SMEM_BYTES);
  cudaFuncSetAttribute(hgemm<M_GELU>,  cudaFuncAttributeMaxDynamicSharedMemorySize, SMEM_BYTES);
  cudaFuncSetAttribute(hgemm<M_RES>,   cudaFuncAttributeMaxDynamicSharedMemorySize, SMEM_BYTES);
  cudaFuncSetAttribute(hgemm<M_SCORE>, cudaFuncAttributeMaxDynamicSharedMemorySize, SMEM_BYTES);

  dim3 tb(32,8);
  tr_split<<<dim3(Dd/32, Dd/32, 1), tb>>>(wq, wqh, wql, Dd, Dd, 0, 0);
  tr_split<<<dim3(Dd/32, Dd/32, 1), tb>>>(wk, wkh, wkl, Dd, Dd, 0, 0);
  tr_split<<<dim3(Dd/32, Dd/32, 1), tb>>>(wv, wvh, wvl, Dd, Dd, 0, 0);
  tr_split<<<dim3(Dd/32, Dd/32, 1), tb>>>(wo, woh, wol, Dd, Dd, 0, 0);
  tr_split<<<dim3(Ff/32, Dd/32, 1), tb>>>(w1, w1h, w1l, Dd, Ff, 0, 0);
  tr_split<<<dim3(Dd/32, Ff/32, 1), tb>>>(w2, w2h, w2l, Ff, Dd, 0, 0);
  conv_split<<<(Bb*Hh*Pp*DKc)/256, 256>>>(r_k, rkh, rkl);
  tr_split<<<dim3(DKc/32, Pp/32, Bb*Hh), tb>>>(r_v, rvh, rvl, Pp, DKc, (long)Pp*DKc, (long)Pp*DKc);

  // 1) LN1
  ln_split<<<Bb*Lq, 256>>>(content, ln1g, ln1b, xnh, xnl);

  // 2) QKV
  dim3 gqkv(Dd/128, (Bb*Lq)/128, 1);
  hgemm<M_QKV><<<gqkv,256,SMEM_BYTES>>>(xnh,xnl, wqh,wql, bq, nullptr, nullptr,nullptr, nullptr, qh,ql, Bb*Lq, Dd, Dd, 0,0,0);
  hgemm<M_QKV><<<gqkv,256,SMEM_BYTES>>>(xnh,xnl, wkh,wkl, bk, nullptr, nullptr,nullptr, nullptr, kh,kl, Bb*Lq, Dd, Dd, 0,0,0);
  hgemm<M_QKV><<<gqkv,256,SMEM_BYTES>>>(xnh,xnl, wvh,wvl, bv, nullptr, nullptr,nullptr, nullptr, vh,vl, Bb*Lq, Dd, Dd, 0,0,0);

  // v -> vt [bh][DK][L]
  tr_bf16<<<dim3(DKc/32, Lq/32, Bb*Hh), tb>>>(vh, vl, vth, vtl, Lq, DKc, (long)Lq*DKc);

  long sQK = (long)Lq*DKc;
  // 3a) qr = q@rk^T  (must precede QK: its epilogue gathers from qr)
  hgemm<M_F32><<<dim3(Pp/128, Lq/128, Bb*Hh),256,SMEM_BYTES>>>(qh,ql, rkh,rkl, nullptr, nullptr, nullptr,nullptr,
                                                    qr, nullptr,nullptr, Lq, Pp, DKc, sQK, (long)Pp*DKc, (long)Lq*Pp);
  // 3b) scores = (q@k^T + gather(qr))*scale + ap, masked  (fused epilogue)
  hgemm<M_SCORE><<<dim3(Lq/128, Lq/128, Bb*Hh),256,SMEM_BYTES>>>(qh,ql, kh,kl, qr, ap, path_map, mask,
                                                    sc, nullptr,nullptr, Lq, Lq, DKc, sQK, sQK, (long)Lq*Lq);
  // 4) fused softmax + scatter
  softmax_scatter<<<dim3(Lq, Bb*Hh),256>>>(sc, path_map, ath, atl, pth, ptl);
  // 5) aout = attn@v ; aout += path@r_v
  hgemm<M_F32><<<dim3(DKc/128, Lq/128, Bb*Hh),256,SMEM_BYTES>>>(ath,atl, vth,vtl, nullptr, nullptr, nullptr,nullptr,
                                                    aout, nullptr,nullptr, Lq, DKc, Lq, (long)Lq*Lq, (long)DKc*Lq, (long)Lq*DKc);
  hgemm<M_ACC><<<dim3(DKc/128, Lq/128, Bb*Hh),256,SMEM_BYTES>>>(pth,ptl, rvh,rvl, nullptr, nullptr, nullptr,nullptr,
                                                    aout, nullptr,nullptr, Lq, DKc, Pp, (long)Lq*Pp, (long)DKc*Pp, (long)Lq*DKc);
  // 6) merge heads
  merge_split<<<(Bb*Hh*Lq*DKc)/256, 256>>>(aout, xnh, xnl);
  // 7) x = merged@wo + bo + content
  hgemm<M_RES><<<dim3(Dd/128,(Bb*Lq)/128,1),256,SMEM_BYTES>>>(xnh,xnl, woh,wol, bo, content, nullptr,nullptr,
                                                    x, nullptr,nullptr, Bb*Lq, Dd, Dd, 0,0,0);
  // 8) LN2
  ln_split<<<Bb*Lq, 256>>>(x, ln2g, ln2b, xnh, xnl);
  // 9) h = gelu(xn@w1 + b1)
  hgemm<M_GELU><<<dim3(Ff/128,(Bb*Lq)/128,1),256,SMEM_BYTES>>>(xnh,xnl, w1h,w1l, b1, nullptr, nullptr,nullptr,
                                                    nullptr, hh,hl, Bb*Lq, Ff, Dd, 0,0,0);
  // 10) out = h@w2 + b2 + x
  hgemm<M_RES><<<dim3(Dd/128,(Bb*Lq)/128,1),256,SMEM_BYTES>>>(hh,hl, w2h,w2l, b2, x, nullptr,nullptr,
                                                    out, nullptr,nullptr, Bb*Lq, Dd, Ff, 0,0,0);
}

// round 7
// speedup vs baseline: 3.6780x; 1.6873x over previous
#include <cuda_runtime.h>
#include <cuda_fp16.h>
#include <cstdint>
#include <math.h>

typedef __half hf;

#define Bb 4
#define Lq 1024
#define Dd 1024
#define Hh 8
#define Pp 1024
#define Ff 4096
#define DKc 128

// ---------------- scratch ----------------
__device__ hf g_xn[Bb*Lq*Dd];
__device__ hf g_q [Bb*Hh*Lq*DKc];
__device__ hf g_k [Bb*Hh*Lq*DKc];
__device__ hf g_v [Bb*Hh*Lq*DKc];
__device__ hf g_vt[Bb*Hh*Lq*DKc];
__device__ hf g_h [Bb*Lq*Ff];
__device__ hf g_attn[(size_t)Bb*Hh*Lq*Lq];
__device__ hf g_path[(size_t)Bb*Hh*Lq*Pp];
__device__ hf g_wqt[Dd*Dd], g_wkt[Dd*Dd], g_wvt[Dd*Dd], g_wot[Dd*Dd];
__device__ hf g_w1t[Dd*Ff], g_w2t[Dd*Ff];
__device__ hf g_rk [Bb*Hh*Pp*DKc];
__device__ hf g_rvt[Bb*Hh*Pp*DKc];
__device__ float g_scores[(size_t)Bb*Hh*Lq*Lq];
__device__ float g_qr[(size_t)Bb*Hh*Lq*Pp];
__device__ float g_aout[Bb*Hh*Lq*DKc];
__device__ float g_x[Bb*Lq*Dd];

// ---------------- helpers ----------------
__device__ __forceinline__ void ldsm4(uint32_t r[4], const hf* p){
  uint32_t a = (uint32_t)__cvta_generic_to_shared(p);
  asm volatile("ldmatrix.sync.aligned.m8n8.x4.shared.b16 {%0,%1,%2,%3},[%4];"
    :"=r"(r[0]),"=r"(r[1]),"=r"(r[2]),"=r"(r[3]):"r"(a));
}
__device__ __forceinline__ void mma_f16(float c[4], const uint32_t a[4], const uint32_t b[2]){
  asm volatile("mma.sync.aligned.m16n8k16.row.col.f32.f16.f16.f32 "
    "{%0,%1,%2,%3},{%4,%5,%6,%7},{%8,%9},{%0,%1,%2,%3};"
    :"+f"(c[0]),"+f"(c[1]),"+f"(c[2]),"+f"(c[3])
    :"r"(a[0]),"r"(a[1]),"r"(a[2]),"r"(a[3]),"r"(b[0]),"r"(b[1]));
}
__device__ __forceinline__ void cpa16(hf* dst, const hf* src){
  uint32_t d = (uint32_t)__cvta_generic_to_shared(dst);
  asm volatile("cp.async.cg.shared.global [%0],[%1],16;"::"r"(d),"l"(src));
}
__device__ __forceinline__ void cpa_commit(){ asm volatile("cp.async.commit_group;"); }
template<int N> __device__ __forceinline__ void cpa_wait(){ asm volatile("cp.async.wait_group %0;"::"n"(N)); }

__device__ __forceinline__ float gelu_f(float u){
  return 0.5f*u*(1.f + tanhf(0.7978845608028654f*(u + 0.044715f*u*u*u)));
}

// ---------------- fp16 tensor-core GEMM, 2-stage cp.async pipeline ----------------
// A[M][K] row-major fp16, B[N][K] row-major fp16 (pre-transposed). 128x128 tile, 8 warps.
#define M_F32   0
#define M_ACC   1
#define M_QKV   2
#define M_GELU  3
#define M_RES   4
#define M_SCORE 5

#define PITCH 40
#define PLANE (128*PITCH)

template<int MODE>
__global__ __launch_bounds__(256)
void hgemm(const hf* __restrict__ A, const hf* __restrict__ Bm,
           const float* __restrict__ bias, const float* __restrict__ res,
           const int* __restrict__ pm, const int* __restrict__ msk,
           float* __restrict__ Cf, hf* __restrict__ Ch,
           int M, int N, int K, long sA, long sB, long sC)
{
  __shared__ hf As[2][PLANE];
  __shared__ hf Bs[2][PLANE];
  long z = blockIdx.z;
  A += z*sA; Bm += z*sB;
  long cbase = z*sC;
  int tid = threadIdx.x, warp = tid>>5, lane = tid&31;
  int bm = blockIdx.y*128, bn = blockIdx.x*128;
  int wm = (warp>>2)*64, wn = (warp&3)*32;
  float c[4][4][4] = {};
  int frag_r = ((lane>>3)&1)*8 + (lane&7);
  int frag_k = (lane>>4)*8;

  // each thread loads 2x16B for A and B per 32-wide K chunk: 128 rows x 2 half-rows
  int r2 = tid>>1, s2 = (tid&1)*16;
  const hf* pa0 = A  + (long)(bm+r2)*K + s2;
  const hf* pb0 = Bm + (long)(bn+r2)*K + s2;

  int T = K >> 5;
  // prologue: tile 0 -> stage 0
  cpa16(&As[0][r2*PITCH + s2],     pa0);
  cpa16(&As[0][r2*PITCH + s2 + 8], pa0 + 8);
  cpa16(&Bs[0][r2*PITCH + s2],     pb0);
  cpa16(&Bs[0][r2*PITCH + s2 + 8], pb0 + 8);
  cpa_commit();

  for(int t=0;t<T;t++){
    if(t+1<T){
      int k0 = (t+1)<<5;
      int st = (t+1)&1;
      cpa16(&As[st][r2*PITCH + s2],     pa0 + k0);
      cpa16(&As[st][r2*PITCH + s2 + 8], pa0 + k0 + 8);
      cpa16(&Bs[st][r2*PITCH + s2],     pb0 + k0);
      cpa16(&Bs[st][r2*PITCH + s2 + 8], pb0 + k0 + 8);
      cpa_commit();
      cpa_wait<1>();
    } else {
      cpa_wait<0>();
    }
    __syncthreads();
    int st = t&1;
#pragma unroll
    for(int kk=0;kk<32;kk+=16){
      uint32_t a4[4][4], b2[4][2];
#pragma unroll
      for(int mi=0;mi<4;mi++)
        ldsm4(a4[mi], &As[st][(wm+mi*16+frag_r)*PITCH + kk + frag_k]);
#pragma unroll
      for(int p=0;p<2;p++){
        uint32_t t4[4];
        ldsm4(t4, &Bs[st][(wn+p*16+frag_r)*PITCH + kk + frag_k]);
        b2[2*p][0]=t4[0]; b2[2*p][1]=t4[2]; b2[2*p+1][0]=t4[1]; b2[2*p+1][1]=t4[3];
      }
#pragma unroll
      for(int mi=0;mi<4;mi++)
#pragma unroll
        for(int ni=0;ni<4;ni++)
          mma_f16(c[mi][ni], a4[mi], b2[ni]);
    }
    __syncthreads();
  }
  // epilogue
#pragma unroll
  for(int mi=0;mi<4;mi++)
#pragma unroll
  for(int ni=0;ni<4;ni++)
#pragma unroll
  for(int hh2=0;hh2<2;hh2++){
    int r = bm + wm + mi*16 + (lane>>2) + hh2*8;
    int cc = bn + wn + ni*8 + (lane&3)*2;
    float v0 = c[mi][ni][hh2*2+0], v1 = c[mi][ni][hh2*2+1];
    if(MODE==M_F32){
      *(float2*)&Cf[cbase + (long)r*N + cc] = make_float2(v0, v1);
    } else if(MODE==M_ACC){
      float2* p = (float2*)&Cf[cbase + (long)r*N + cc];
      float2 o = *p;
      *p = make_float2(o.x+v0, o.y+v1);
    } else if(MODE==M_RES){
      v0 += bias[cc]   + res[(long)r*N + cc];
      v1 += bias[cc+1] + res[(long)r*N + cc + 1];
      *(float2*)&Cf[cbase + (long)r*N + cc] = make_float2(v0, v1);
    } else if(MODE==M_GELU){
      __half2 hv; hv.x = __float2half_rn(gelu_f(v0 + bias[cc])); hv.y = __float2half_rn(gelu_f(v1 + bias[cc+1]));
      *(__half2*)&Ch[(long)r*N + cc] = hv;
    } else if(MODE==M_QKV){
      __half2 hv; hv.x = __float2half_rn(v0 + bias[cc]); hv.y = __float2half_rn(v1 + bias[cc+1]);
      int b = r>>10, l = r&1023, hd = cc>>7, d = cc&127;
      *(__half2*)&Ch[(((long)(b*Hh+hd))*Lq + l)*DKc + d] = hv;
    } else if(MODE==M_SCORE){
      const float scale = 0.08838834764831845f;
      long b = z >> 3;
      long rowq = z*((long)Lq*Pp) + (long)r*Pp;
      long rowm = b*((long)Lq*Lq) + (long)r*Lq;
      long rowa = z*((long)Lq*Lq) + (long)r*Lq;
      int p0 = pm[rowm + cc], p1 = pm[rowm + cc + 1];
      int m0 = msk[rowm + cc], m1 = msk[rowm + cc + 1];
      float s0v = (v0 + bias[rowq + p0])*scale + res[rowa + cc];
      float s1v = (v1 + bias[rowq + p1])*scale + res[rowa + cc + 1];
      if(m0==0) s0v = -1e9f;
      if(m1==0) s1v = -1e9f;
      *(float2*)&Cf[cbase + (long)r*N + cc] = make_float2(s0v, s1v);
    }
  }
}

// ---------------- LayerNorm -> fp16 ----------------
__global__ void ln_h(const float* __restrict__ x, const float* __restrict__ g,
                     const float* __restrict__ b, hf* __restrict__ y){
  __shared__ float red[256];
  int row = blockIdx.x;
  const float* xr = x + (size_t)row*Dd;
  float v[4]; float s = 0.f;
#pragma unroll
  for(int i=0;i<4;i++){ v[i] = xr[threadIdx.x + i*256]; s += v[i]; }
  red[threadIdx.x] = s; __syncthreads();
  for(int o=128;o>0;o>>=1){ if(threadIdx.x<o) red[threadIdx.x]+=red[threadIdx.x+o]; __syncthreads(); }
  float mean = red[0]*(1.f/Dd); __syncthreads();
  float s2 = 0.f;
#pragma unroll
  for(int i=0;i<4;i++){ float d = v[i]-mean; s2 += d*d; }
  red[threadIdx.x] = s2; __syncthreads();
  for(int o=128;o>0;o>>=1){ if(threadIdx.x<o) red[threadIdx.x]+=red[threadIdx.x+o]; __syncthreads(); }
  float inv = rsqrtf(red[0]*(1.f/Dd) + 1e-6f);
#pragma unroll
  for(int i=0;i<4;i++){
    int cidx = threadIdx.x + i*256;
    y[(long)row*Dd + cidx] = __float2half_rn(g[cidx]*(v[i]-mean)*inv + b[cidx]);
  }
}

// ---------------- weight prep ----------------
__global__ void tr_h(const float* __restrict__ in, hf* __restrict__ o,
                     int rows, int cols, long sIn, long sOut){
  __shared__ float t[32][33];
  long z = blockIdx.z;
  in += z*sIn; o += z*sOut;
  int bx = blockIdx.x*32, by = blockIdx.y*32;
  int tx = threadIdx.x, ty = threadIdx.y;
#pragma unroll
  for(int i=0;i<4;i++)
    t[ty+i*8][tx] = in[(long)(by+ty+i*8)*cols + bx+tx];
  __syncthreads();
#pragma unroll
  for(int i=0;i<4;i++)
    o[(long)(bx+ty+i*8)*rows + by+tx] = __float2half_rn(t[tx][ty+i*8]);
}
__global__ void conv_h(const float* __restrict__ in, hf* __restrict__ o){
  int idx = blockIdx.x*256 + threadIdx.x;
  o[idx] = __float2half_rn(in[idx]);
}
__global__ void tr_h16(const hf* __restrict__ in, hf* __restrict__ o,
                       int rows, int cols, long s){
  __shared__ hf t[32][33];
  long z = blockIdx.z;
  in += z*s; o += z*s;
  int bx = blockIdx.x*32, by = blockIdx.y*32;
  int tx = threadIdx.x, ty = threadIdx.y;
#pragma unroll
  for(int i=0;i<4;i++)
    t[ty+i*8][tx] = in[(long)(by+ty+i*8)*cols + bx+tx];
  __syncthreads();
#pragma unroll
  for(int i=0;i<4;i++)
    o[(long)(bx+ty+i*8)*rows + by+tx] = t[tx][ty+i*8];
}

// ---------------- fused softmax + scatter ----------------
__global__ void softmax_scatter(const float* __restrict__ scores, const int* __restrict__ pm,
                                hf* __restrict__ outa, hf* __restrict__ outp){
  __shared__ float red[256];
  __shared__ float sp[Pp];
  int bh = blockIdx.y;
  int b  = bh >> 3;
  int i  = blockIdx.x;
  const float* srow = scores + ((size_t)bh*Lq + i)*Lq;
  const int*   prow = pm + ((size_t)b*Lq + i)*Lq;
#pragma unroll
  for(int k=0;k<4;k++) sp[threadIdx.x + k*256] = 0.f;
  float v[4]; float mx = -3.0e38f;
#pragma unroll
  for(int k=0;k<4;k++){
    v[k] = srow[threadIdx.x + k*256];
    mx = fmaxf(mx, v[k]);
  }
  red[threadIdx.x] = mx; __syncthreads();
  for(int o=128;o>0;o>>=1){ if(threadIdx.x<o) red[threadIdx.x]=fmaxf(red[threadIdx.x],red[threadIdx.x+o]); __syncthreads(); }
  mx = red[0]; __syncthreads();
  float s = 0.f;
#pragma unroll
  for(int k=0;k<4;k++){ v[k] = expf(v[k]-mx); s += v[k]; }
  red[threadIdx.x] = s; __syncthreads();
  for(int o=128;o>0;o>>=1){ if(threadIdx.x<o) red[threadIdx.x]+=red[threadIdx.x+o]; __syncthreads(); }
  float inv = 1.f/red[0];
  long obase = ((size_t)bh*Lq + i)*Lq;
#pragma unroll
  for(int k=0;k<4;k++){
    int j = threadIdx.x + k*256;
    float a = v[k]*inv;
    outa[obase + j] = __float2half_rn(a);
    atomicAdd(&sp[prow[j]], a);
  }
  __syncthreads();
  long pbase = ((size_t)bh*Lq + i)*Pp;
#pragma unroll
  for(int k=0;k<4;k++){
    int cidx = threadIdx.x + k*256;
    outp[pbase + cidx] = __float2half_rn(sp[cidx]);
  }
}

// ---------------- merge heads fp32 [B,H,L,DK] -> fp16 [B,L,D] ----------------
__global__ void merge_h(const float* __restrict__ in, hf* __restrict__ o){
  int idx = blockIdx.x*256 + threadIdx.x;
  float v = in[idx];
  int d = idx & 127;
  int l = (idx >> 7) & 1023;
  int hd = (idx >> 17) & 7;
  int b = idx >> 20;
  o[((long)(b*Lq + l))*Dd + hd*DKc + d] = __float2half_rn(v);
}

// ---------------- launch ----------------
extern "C" void kernel_launch(void* const* d_in, const int* in_sizes, int n_in,
                              void* d_out, int out_size){
  const float* content = (const float*)d_in[0];
  const int*   mask    = (const int*)  d_in[1];
  const float* r_k     = (const float*)d_in[2];
  const float* r_v     = (const float*)d_in[3];
  const int*   path_map= (const int*)  d_in[4];
  const float* ap      = (const float*)d_in[5];
  const float* wq = (const float*)d_in[6];  const float* bq = (const float*)d_in[7];
  const float* wk = (const float*)d_in[8];  const float* bk = (const float*)d_in[9];
  const float* wv = (const float*)d_in[10]; const float* bv = (const float*)d_in[11];
  const float* wo = (const float*)d_in[12]; const float* bo = (const float*)d_in[13];
  const float* ln1g = (const float*)d_in[14]; const float* ln1b = (const float*)d_in[15];
  const float* ln2g = (const float*)d_in[16]; const float* ln2b = (const float*)d_in[17];
  const float* w1 = (const float*)d_in[18]; const float* b1 = (const float*)d_in[19];
  const float* w2 = (const float*)d_in[20]; const float* b2 = (const float*)d_in[21];
  float* out = (float*)d_out;

  hf *xn,*q,*k,*v,*vt,*h,*at,*pt,*wqt,*wkt,*wvt,*wot,*w1t,*w2t,*rk,*rvt;
  float *sc,*qr,*aout,*x;
  cudaGetSymbolAddress((void**)&xn, g_xn);
  cudaGetSymbolAddress((void**)&q, g_q);   cudaGetSymbolAddress((void**)&k, g_k);
  cudaGetSymbolAddress((void**)&v, g_v);   cudaGetSymbolAddress((void**)&vt, g_vt);
  cudaGetSymbolAddress((void**)&h, g_h);
  cudaGetSymbolAddress((void**)&at, g_attn); cudaGetSymbolAddress((void**)&pt, g_path);
  cudaGetSymbolAddress((void**)&wqt, g_wqt); cudaGetSymbolAddress((void**)&wkt, g_wkt);
  cudaGetSymbolAddress((void**)&wvt, g_wvt); cudaGetSymbolAddress((void**)&wot, g_wot);
  cudaGetSymbolAddress((void**)&w1t, g_w1t); cudaGetSymbolAddress((void**)&w2t, g_w2t);
  cudaGetSymbolAddress((void**)&rk, g_rk);   cudaGetSymbolAddress((void**)&rvt, g_rvt);
  cudaGetSymbolAddress((void**)&sc, g_scores);
  cudaGetSymbolAddress((void**)&qr, g_qr);
  cudaGetSymbolAddress((void**)&aout, g_aout);
  cudaGetSymbolAddress((void**)&x, g_x);

  dim3 tb(32,8);
  tr_h<<<dim3(Dd/32, Dd/32, 1), tb>>>(wq, wqt, Dd, Dd, 0, 0);
  tr_h<<<dim3(Dd/32, Dd/32, 1), tb>>>(wk, wkt, Dd, Dd, 0, 0);
  tr_h<<<dim3(Dd/32, Dd/32, 1), tb>>>(wv, wvt, Dd, Dd, 0, 0);
  tr_h<<<dim3(Dd/32, Dd/32, 1), tb>>>(wo, wot, Dd, Dd, 0, 0);
  tr_h<<<dim3(Ff/32, Dd/32, 1), tb>>>(w1, w1t, Dd, Ff, 0, 0);
  tr_h<<<dim3(Dd/32, Ff/32, 1), tb>>>(w2, w2t, Ff, Dd, 0, 0);
  conv_h<<<(Bb*Hh*Pp*DKc)/256, 256>>>(r_k, rk);
  tr_h<<<dim3(DKc/32, Pp/32, Bb*Hh), tb>>>(r_v, rvt, Pp, DKc, (long)Pp*DKc, (long)Pp*DKc);

  // 1) LN1
  ln_h<<<Bb*Lq, 256>>>(content, ln1g, ln1b, xn);

  // 2) QKV
  dim3 gqkv(Dd/128, (Bb*Lq)/128, 1);
  hgemm<M_QKV><<<gqkv,256>>>(xn, wqt, bq, nullptr, nullptr,nullptr, nullptr, q, Bb*Lq, Dd, Dd, 0,0,0);
  hgemm<M_QKV><<<gqkv,256>>>(xn, wkt, bk, nullptr, nullptr,nullptr, nullptr, k, Bb*Lq, Dd, Dd, 0,0,0);
  hgemm<M_QKV><<<gqkv,256>>>(xn, wvt, bv, nullptr, nullptr,nullptr, nullptr, v, Bb*Lq, Dd, Dd, 0,0,0);

  // v -> vt [bh][DK][L]
  tr_h16<<<dim3(DKc/32, Lq/32, Bb*Hh), tb>>>(v, vt, Lq, DKc, (long)Lq*DKc);

  long sQK = (long)Lq*DKc;
  // 3a) qr = q@rk^T
  hgemm<M_F32><<<dim3(Pp/128, Lq/128, Bb*Hh),256>>>(q, rk, nullptr, nullptr, nullptr,nullptr,
      qr, nullptr, Lq, Pp, DKc, sQK, (long)Pp*DKc, (long)Lq*Pp);
  // 3b) scores = (q@k^T + gather(qr))*scale + ap, masked
  hgemm<M_SCORE><<<dim3(Lq/128, Lq/128, Bb*Hh),256>>>(q, k, qr, ap, path_map, mask,
      sc, nullptr, Lq, Lq, DKc, sQK, sQK, (long)Lq*Lq);
  // 4) fused softmax + scatter
  softmax_scatter<<<dim3(Lq, Bb*Hh),256>>>(sc, path_map, at, pt);
  // 5) aout = attn@v ; aout += path@r_v
  hgemm<M_F32><<<dim3(DKc/128, Lq/128, Bb*Hh),256>>>(at, vt, nullptr, nullptr, nullptr,nullptr,
      aout, nullptr, Lq, DKc, Lq, (long)Lq*Lq, (long)DKc*Lq, (long)Lq*DKc);
  hgemm<M_ACC><<<dim3(DKc/128, Lq/128, Bb*Hh),256>>>(pt, rvt, nullptr, nullptr, nullptr,nullptr,
      aout, nullptr, Lq, DKc, Pp, (long)Lq*Pp, (long)DKc*Pp, (long)Lq*DKc);
  // 6) merge heads
  merge_h<<<(Bb*Hh*Lq*DKc)/256, 256>>>(aout, xn);
  // 7) x = merged@wo + bo + content
  hgemm<M_RES><<<dim3(Dd/128,(Bb*Lq)/128,1),256>>>(xn, wot, bo, content, nullptr,nullptr,
      x, nullptr, Bb*Lq, Dd, Dd, 0,0,0);
  // 8) LN2
  ln_h<<<Bb*Lq, 256>>>(x, ln2g, ln2b, xn);
  // 9) h = gelu(xn@w1 + b1)
  hgemm<M_GELU><<<dim3(Ff/128,(Bb*Lq)/128,1),256>>>(xn, w1t, b1, nullptr, nullptr,nullptr,
      nullptr, h, Bb*Lq, Ff, Dd, 0,0,0);
  // 10) out = h@w2 + b2 + x
  hgemm<M_RES><<<dim3(Dd/128,(Bb*Lq)/128,1),256>>>(h, w2t, b2, x, nullptr,nullptr,
      out, nullptr, Bb*Lq, Dd, Ff, 0,0,0);
}

// round 8
// speedup vs baseline: 3.8527x; 1.0475x over previous
#include <cuda_runtime.h>
#include <cuda_fp16.h>
#include <cstdint>
#include <math.h>

typedef __half hf;

#define Bb 4
#define Lq 1024
#define Dd 1024
#define Hh 8
#define Pp 1024
#define Ff 4096
#define DKc 128

#define SQKV ((long)Bb*Hh*Lq*DKc)

// ---------------- scratch ----------------
__device__ hf g_xn[Bb*Lq*Dd];
__device__ hf g_qkv[3*Bb*Hh*Lq*DKc];      // q | k | v, each [B,H,L,DK]
__device__ hf g_vt[Bb*Hh*Lq*DKc];         // [bh][DK][L]
__device__ hf g_h [Bb*Lq*Ff];
__device__ hf g_attn[(size_t)Bb*Hh*Lq*Lq];
__device__ hf g_path[(size_t)Bb*Hh*Lq*Pp];
__device__ hf g_w4t[4*Dd*Dd];             // wq^T | wk^T | wv^T | wo^T
__device__ hf g_w1t[Dd*Ff], g_w2t[Dd*Ff];
__device__ hf g_rk [Bb*Hh*Pp*DKc];
__device__ hf g_rvt[Bb*Hh*Pp*DKc];
__device__ float g_scores[(size_t)Bb*Hh*Lq*Lq];
__device__ float g_qr[(size_t)Bb*Hh*Lq*Pp];
__device__ float g_x[Bb*Lq*Dd];

// ---------------- helpers ----------------
__device__ __forceinline__ void ldsm4(uint32_t r[4], const hf* p){
  uint32_t a = (uint32_t)__cvta_generic_to_shared(p);
  asm volatile("ldmatrix.sync.aligned.m8n8.x4.shared.b16 {%0,%1,%2,%3},[%4];"
    :"=r"(r[0]),"=r"(r[1]),"=r"(r[2]),"=r"(r[3]):"r"(a));
}
__device__ __forceinline__ void mma_f16(float c[4], const uint32_t a[4], const uint32_t b[2]){
  asm volatile("mma.sync.aligned.m16n8k16.row.col.f32.f16.f16.f32 "
    "{%0,%1,%2,%3},{%4,%5,%6,%7},{%8,%9},{%0,%1,%2,%3};"
    :"+f"(c[0]),"+f"(c[1]),"+f"(c[2]),"+f"(c[3])
    :"r"(a[0]),"r"(a[1]),"r"(a[2]),"r"(a[3]),"r"(b[0]),"r"(b[1]));
}
__device__ __forceinline__ void cpa16(hf* dst, const hf* src){
  uint32_t d = (uint32_t)__cvta_generic_to_shared(dst);
  asm volatile("cp.async.cg.shared.global [%0],[%1],16;"::"r"(d),"l"(src));
}
__device__ __forceinline__ void cpa_commit(){ asm volatile("cp.async.commit_group;"); }
template<int N> __device__ __forceinline__ void cpa_wait(){ asm volatile("cp.async.wait_group %0;"::"n"(N)); }

__device__ __forceinline__ float gelu_f(float u){
  return 0.5f*u*(1.f + tanhf(0.7978845608028654f*(u + 0.044715f*u*u*u)));
}

// ---------------- fp16 tensor-core GEMM, 2-stage cp.async pipeline ----------------
// A[M][K] row-major fp16, B[N][K] row-major fp16 (pre-transposed). 128x128 tile, 8 warps.
// Optional second K-segment (A2/B2, K2) accumulated in registers (same output tile).
#define M_F32   0
#define M_QKV   2
#define M_GELU  3
#define M_RES   4
#define M_SCORE 5
#define M_MERGE 6

#define PITCH 40
#define PLANE (128*PITCH)

template<int MODE>
__global__ __launch_bounds__(256)
void hgemm(const hf* __restrict__ A, const hf* __restrict__ Bm,
           const hf* __restrict__ A2, const hf* __restrict__ B2,
           const float* __restrict__ bias, const float* __restrict__ bias2,
           const float* __restrict__ bias3,
           const float* __restrict__ res,
           const int* __restrict__ pm, const int* __restrict__ msk,
           float* __restrict__ Cf, hf* __restrict__ Ch,
           int N, int K, int K2,
           long sA, long sB, long sA2, long sB2, long sC)
{
  __shared__ hf As[2][PLANE];
  __shared__ hf Bs[2][PLANE];
  long z = blockIdx.z;
  long cbase = z*sC;
  int tid = threadIdx.x, warp = tid>>5, lane = tid&31;
  int bm = blockIdx.y*128, bn = blockIdx.x*128;
  int wm = (warp>>2)*64, wn = (warp&3)*32;
  float c[4][4][4] = {};
  int frag_r = ((lane>>3)&1)*8 + (lane&7);
  int frag_k = (lane>>4)*8;

  int r2 = tid>>1, s2 = (tid&1)*16;
  const hf* pa1 = A  + z*sA + (long)(bm+r2)*K + s2;
  const hf* pb1 = Bm + z*sB + (long)(bn+r2)*K + s2;
  const hf* pa2 = (MODE==M_MERGE) ? (A2 + z*sA2 + (long)(bm+r2)*K2 + s2) : pa1;
  const hf* pb2 = (MODE==M_MERGE) ? (B2 + z*sB2 + (long)(bn+r2)*K2 + s2) : pb1;

  const int T1 = K >> 5;
  const int T  = T1 + (K2 >> 5);

  auto ld = [&](int cchunk){
    int st = cchunk&1;
    const hf *pa, *pb; int off;
    if(cchunk < T1){ pa = pa1; pb = pb1; off = cchunk<<5; }
    else           { pa = pa2; pb = pb2; off = (cchunk-T1)<<5; }
    cpa16(&As[st][r2*PITCH + s2],     pa + off);
    cpa16(&As[st][r2*PITCH + s2 + 8], pa + off + 8);
    cpa16(&Bs[st][r2*PITCH + s2],     pb + off);
    cpa16(&Bs[st][r2*PITCH + s2 + 8], pb + off + 8);
  };

  ld(0); cpa_commit();
  for(int t=0;t<T;t++){
    if(t+1<T){
      ld(t+1); cpa_commit();
      cpa_wait<1>();
    } else {
      cpa_wait<0>();
    }
    __syncthreads();
    int st = t&1;
#pragma unroll
    for(int kk=0;kk<32;kk+=16){
      uint32_t a4[4][4], b2[4][2];
#pragma unroll
      for(int mi=0;mi<4;mi++)
        ldsm4(a4[mi], &As[st][(wm+mi*16+frag_r)*PITCH + kk + frag_k]);
#pragma unroll
      for(int p=0;p<2;p++){
        uint32_t t4[4];
        ldsm4(t4, &Bs[st][(wn+p*16+frag_r)*PITCH + kk + frag_k]);
        b2[2*p][0]=t4[0]; b2[2*p][1]=t4[2]; b2[2*p+1][0]=t4[1]; b2[2*p+1][1]=t4[3];
      }
#pragma unroll
      for(int mi=0;mi<4;mi++)
#pragma unroll
        for(int ni=0;ni<4;ni++)
          mma_f16(c[mi][ni], a4[mi], b2[ni]);
    }
    __syncthreads();
  }
  // epilogue
#pragma unroll
  for(int mi=0;mi<4;mi++)
#pragma unroll
  for(int ni=0;ni<4;ni++)
#pragma unroll
  for(int hh2=0;hh2<2;hh2++){
    int r = bm + wm + mi*16 + (lane>>2) + hh2*8;
    int cc = bn + wn + ni*8 + (lane&3)*2;
    float v0 = c[mi][ni][hh2*2+0], v1 = c[mi][ni][hh2*2+1];
    if(MODE==M_F32){
      *(float2*)&Cf[cbase + (long)r*N + cc] = make_float2(v0, v1);
    } else if(MODE==M_RES){
      v0 += bias[cc]   + res[(long)r*N + cc];
      v1 += bias[cc+1] + res[(long)r*N + cc + 1];
      *(float2*)&Cf[cbase + (long)r*N + cc] = make_float2(v0, v1);
    } else if(MODE==M_GELU){
      __half2 hv; hv.x = __float2half_rn(gelu_f(v0 + bias[cc])); hv.y = __float2half_rn(gelu_f(v1 + bias[cc+1]));
      *(__half2*)&Ch[(long)r*N + cc] = hv;
    } else if(MODE==M_QKV){
      int buf = cc>>10, c10 = cc&1023;
      const float* bp = (buf==0)? bias : (buf==1)? bias2 : bias3;
      __half2 hv; hv.x = __float2half_rn(v0 + bp[c10]); hv.y = __float2half_rn(v1 + bp[c10+1]);
      int bI = r>>10, l = r&1023, hd = c10>>7, d = c10&127;
      *(__half2*)&Ch[(long)buf*SQKV + (((long)(bI*Hh+hd))*Lq + l)*DKc + d] = hv;
    } else if(MODE==M_MERGE){
      long bI = z>>3, hd = z&7;
      __half2 hv; hv.x = __float2half_rn(v0); hv.y = __float2half_rn(v1);
      *(__half2*)&Ch[((bI*Lq + r))*Dd + hd*DKc + cc] = hv;
    } else if(MODE==M_SCORE){
      const float scale = 0.08838834764831845f;
      long bI = z >> 3;
      long rowq = z*((long)Lq*Pp) + (long)r*Pp;
      long rowm = bI*((long)Lq*Lq) + (long)r*Lq;
      long rowa = z*((long)Lq*Lq) + (long)r*Lq;
      int p0 = pm[rowm + cc], p1 = pm[rowm + cc + 1];
      int m0 = msk[rowm + cc], m1 = msk[rowm + cc + 1];
      float s0v = (v0 + bias[rowq + p0])*scale + res[rowa + cc];
      float s1v = (v1 + bias[rowq + p1])*scale + res[rowa + cc + 1];
      if(m0==0) s0v = -1e9f;
      if(m1==0) s1v = -1e9f;
      *(float2*)&Cf[cbase + (long)r*N + cc] = make_float2(s0v, s1v);
    }
  }
}

// ---------------- LayerNorm -> fp16 ----------------
__global__ void ln_h(const float* __restrict__ x, const float* __restrict__ g,
                     const float* __restrict__ b, hf* __restrict__ y){
  __shared__ float red[256];
  int row = blockIdx.x;
  const float* xr = x + (size_t)row*Dd;
  float v[4]; float s = 0.f;
#pragma unroll
  for(int i=0;i<4;i++){ v[i] = xr[threadIdx.x + i*256]; s += v[i]; }
  red[threadIdx.x] = s; __syncthreads();
  for(int o=128;o>0;o>>=1){ if(threadIdx.x<o) red[threadIdx.x]+=red[threadIdx.x+o]; __syncthreads(); }
  float mean = red[0]*(1.f/Dd); __syncthreads();
  float s2 = 0.f;
#pragma unroll
  for(int i=0;i<4;i++){ float d = v[i]-mean; s2 += d*d; }
  red[threadIdx.x] = s2; __syncthreads();
  for(int o=128;o>0;o>>=1){ if(threadIdx.x<o) red[threadIdx.x]+=red[threadIdx.x+o]; __syncthreads(); }
  float inv = rsqrtf(red[0]*(1.f/Dd) + 1e-6f);
#pragma unroll
  for(int i=0;i<4;i++){
    int cidx = threadIdx.x + i*256;
    y[(long)row*Dd + cidx] = __float2half_rn(g[cidx]*(v[i]-mean)*inv + b[cidx]);
  }
}

// ---------------- weight prep ----------------
// 4x DxD transpose: z selects {wq,wk,wv,wo} -> g_w4t + z*Dd*Dd
__global__ void tr_many(const float* __restrict__ wq, const float* __restrict__ wk,
                        const float* __restrict__ wv, const float* __restrict__ wo,
                        hf* __restrict__ o4){
  __shared__ float t[32][33];
  long z = blockIdx.z;
  const float* in = (z==0)? wq : (z==1)? wk : (z==2)? wv : wo;
  hf* o = o4 + z*(long)Dd*Dd;
  int bx = blockIdx.x*32, by = blockIdx.y*32;
  int tx = threadIdx.x, ty = threadIdx.y;
#pragma unroll
  for(int i=0;i<4;i++)
    t[ty+i*8][tx] = in[(long)(by+ty+i*8)*Dd + bx+tx];
  __syncthreads();
#pragma unroll
  for(int i=0;i<4;i++)
    o[(long)(bx+ty+i*8)*Dd + by+tx] = __float2half_rn(t[tx][ty+i*8]);
}
__global__ void tr_h(const float* __restrict__ in, hf* __restrict__ o,
                     int rows, int cols){
  __shared__ float t[32][33];
  int bx = blockIdx.x*32, by = blockIdx.y*32;
  int tx = threadIdx.x, ty = threadIdx.y;
#pragma unroll
  for(int i=0;i<4;i++)
    t[ty+i*8][tx] = in[(long)(by+ty+i*8)*cols + bx+tx];
  __syncthreads();
#pragma unroll
  for(int i=0;i<4;i++)
    o[(long)(bx+ty+i*8)*rows + by+tx] = __float2half_rn(t[tx][ty+i*8]);
}
// per-head: convert rk (straight) + transpose rv, same tile coords
__global__ void prep_r(const float* __restrict__ rk, const float* __restrict__ rv,
                       hf* __restrict__ rkh, hf* __restrict__ rvt){
  __shared__ float t[32][33];
  long z = blockIdx.z;
  const float* ik = rk + z*(long)Pp*DKc;
  const float* iv = rv + z*(long)Pp*DKc;
  hf* ok = rkh + z*(long)Pp*DKc;
  hf* ov = rvt + z*(long)Pp*DKc;
  int bx = blockIdx.x*32, by = blockIdx.y*32;  // bx: DKc, by: Pp
  int tx = threadIdx.x, ty = threadIdx.y;
#pragma unroll
  for(int i=0;i<4;i++){
    long src = (long)(by+ty+i*8)*DKc + bx+tx;
    t[ty+i*8][tx] = iv[src];
    ok[src] = __float2half_rn(ik[src]);
  }
  __syncthreads();
#pragma unroll
  for(int i=0;i<4;i++)
    ov[(long)(bx+ty+i*8)*Pp + by+tx] = __float2half_rn(t[tx][ty+i*8]);
}
// v -> vt [bh][DK][L] (fp16 transpose)
__global__ void tr_h16(const hf* __restrict__ in, hf* __restrict__ o,
                       int rows, int cols, long s){
  __shared__ hf t[32][33];
  long z = blockIdx.z;
  in += z*s; o += z*s;
  int bx = blockIdx.x*32, by = blockIdx.y*32;
  int tx = threadIdx.x, ty = threadIdx.y;
#pragma unroll
  for(int i=0;i<4;i++)
    t[ty+i*8][tx] = in[(long)(by+ty+i*8)*cols + bx+tx];
  __syncthreads();
#pragma unroll
  for(int i=0;i<4;i++)
    o[(long)(bx+ty+i*8)*rows + by+tx] = t[tx][ty+i*8];
}

// ---------------- fused softmax + scatter ----------------
__global__ void softmax_scatter(const float* __restrict__ scores, const int* __restrict__ pm,
                                hf* __restrict__ outa, hf* __restrict__ outp){
  __shared__ float red[256];
  __shared__ float sp[Pp];
  int bh = blockIdx.y;
  int b  = bh >> 3;
  int i  = blockIdx.x;
  const float* srow = scores + ((size_t)bh*Lq + i)*Lq;
  const int*   prow = pm + ((size_t)b*Lq + i)*Lq;
#pragma unroll
  for(int k=0;k<4;k++) sp[threadIdx.x + k*256] = 0.f;
  float v[4]; float mx = -3.0e38f;
#pragma unroll
  for(int k=0;k<4;k++){
    v[k] = srow[threadIdx.x + k*256];
    mx = fmaxf(mx, v[k]);
  }
  red[threadIdx.x] = mx; __syncthreads();
  for(int o=128;o>0;o>>=1){ if(threadIdx.x<o) red[threadIdx.x]=fmaxf(red[threadIdx.x],red[threadIdx.x+o]); __syncthreads(); }
  mx = red[0]; __syncthreads();
  float s = 0.f;
#pragma unroll
  for(int k=0;k<4;k++){ v[k] = expf(v[k]-mx); s += v[k]; }
  red[threadIdx.x] = s; __syncthreads();
  for(int o=128;o>0;o>>=1){ if(threadIdx.x<o) red[threadIdx.x]+=red[threadIdx.x+o]; __syncthreads(); }
  float inv = 1.f/red[0];
  long obase = ((size_t)bh*Lq + i)*Lq;
#pragma unroll
  for(int k=0;k<4;k++){
    int j = threadIdx.x + k*256;
    float a = v[k]*inv;
    outa[obase + j] = __float2half_rn(a);
    atomicAdd(&sp[prow[j]], a);
  }
  __syncthreads();
  long pbase = ((size_t)bh*Lq + i)*Pp;
#pragma unroll
  for(int k=0;k<4;k++){
    int cidx = threadIdx.x + k*256;
    outp[pbase + cidx] = __float2half_rn(sp[cidx]);
  }
}

// ---------------- launch ----------------
extern "C" void kernel_launch(void* const* d_in, const int* in_sizes, int n_in,
                              void* d_out, int out_size){
  const float* content = (const float*)d_in[0];
  const int*   mask    = (const int*)  d_in[1];
  const float* r_k     = (const float*)d_in[2];
  const float* r_v     = (const float*)d_in[3];
  const int*   path_map= (const int*)  d_in[4];
  const float* ap      = (const float*)d_in[5];
  const float* wq = (const float*)d_in[6];  const float* bq = (const float*)d_in[7];
  const float* wk = (const float*)d_in[8];  const float* bk = (const float*)d_in[9];
  const float* wv = (const float*)d_in[10]; const float* bv = (const float*)d_in[11];
  const float* wo = (const float*)d_in[12]; const float* bo = (const float*)d_in[13];
  const float* ln1g = (const float*)d_in[14]; const float* ln1b = (const float*)d_in[15];
  const float* ln2g = (const float*)d_in[16]; const float* ln2b = (const float*)d_in[17];
  const float* w1 = (const float*)d_in[18]; const float* b1 = (const float*)d_in[19];
  const float* w2 = (const float*)d_in[20]; const float* b2 = (const float*)d_in[21];
  float* out = (float*)d_out;

  hf *xn,*qkv,*vt,*h,*at,*pt,*w4t,*w1t,*w2t,*rk,*rvt;
  float *sc,*qr,*x;
  cudaGetSymbolAddress((void**)&xn, g_xn);
  cudaGetSymbolAddress((void**)&qkv, g_qkv);
  cudaGetSymbolAddress((void**)&vt, g_vt);
  cudaGetSymbolAddress((void**)&h, g_h);
  cudaGetSymbolAddress((void**)&at, g_attn); cudaGetSymbolAddress((void**)&pt, g_path);
  cudaGetSymbolAddress((void**)&w4t, g_w4t);
  cudaGetSymbolAddress((void**)&w1t, g_w1t); cudaGetSymbolAddress((void**)&w2t, g_w2t);
  cudaGetSymbolAddress((void**)&rk, g_rk);   cudaGetSymbolAddress((void**)&rvt, g_rvt);
  cudaGetSymbolAddress((void**)&sc, g_scores);
  cudaGetSymbolAddress((void**)&qr, g_qr);
  cudaGetSymbolAddress((void**)&x, g_x);

  hf* q = qkv;
  hf* k = qkv + SQKV;
  hf* v = qkv + 2*SQKV;
  long sQK = (long)Lq*DKc;

  dim3 tb(32,8);
  // prep (launches 1-4)
  tr_many<<<dim3(Dd/32, Dd/32, 4), tb>>>(wq, wk, wv, wo, w4t);
  tr_h<<<dim3(Ff/32, Dd/32), tb>>>(w1, w1t, Dd, Ff);
  tr_h<<<dim3(Dd/32, Ff/32), tb>>>(w2, w2t, Ff, Dd);
  prep_r<<<dim3(DKc/32, Pp/32, Bb*Hh), tb>>>(r_k, r_v, rk, rvt);

  // 5) LN1
  ln_h<<<Bb*Lq, 256>>>(content, ln1g, ln1b, xn);

  // 6) combined QKV GEMM (N=3072)  <- ncu -s 5 captures this
  hgemm<M_QKV><<<dim3(3*Dd/128, (Bb*Lq)/128, 1),256>>>(
      xn, w4t, nullptr,nullptr, bq, bk, bv, nullptr, nullptr,nullptr,
      nullptr, qkv, 3*Dd, Dd, 0, 0,0,0,0, 0);

  // 7) v -> vt
  tr_h16<<<dim3(DKc/32, Lq/32, Bb*Hh), tb>>>(v, vt, Lq, DKc, sQK);

  // 8) qr = q@rk^T
  hgemm<M_F32><<<dim3(Pp/128, Lq/128, Bb*Hh),256>>>(
      q, rk, nullptr,nullptr, nullptr,nullptr,nullptr, nullptr, nullptr,nullptr,
      qr, nullptr, Pp, DKc, 0, sQK, (long)Pp*DKc, 0,0, (long)Lq*Pp);

  // 9) scores = (q@k^T + gather(qr))*scale + ap, masked
  hgemm<M_SCORE><<<dim3(Lq/128, Lq/128, Bb*Hh),256>>>(
      q, k, nullptr,nullptr, qr, nullptr,nullptr, ap, path_map, mask,
      sc, nullptr, Lq, DKc, 0, sQK, sQK, 0,0, (long)Lq*Lq);

  // 10) fused softmax + scatter
  softmax_scatter<<<dim3(Lq, Bb*Hh),256>>>(sc, path_map, at, pt);

  // 11) merged: out = attn@v + path@r_v -> xn (head-merged fp16)
  hgemm<M_MERGE><<<dim3(1, Lq/128, Bb*Hh),256>>>(
      at, vt, pt, rvt, nullptr,nullptr,nullptr, nullptr, nullptr,nullptr,
      nullptr, xn, DKc, Lq, Pp,
      (long)Lq*Lq, (long)DKc*Lq, (long)Lq*Pp, (long)DKc*Pp, 0);

  // 12) x = merged@wo + bo + content
  hgemm<M_RES><<<dim3(Dd/128,(Bb*Lq)/128,1),256>>>(
      xn, w4t + 3*(long)Dd*Dd, nullptr,nullptr, bo, nullptr,nullptr, content, nullptr,nullptr,
      x, nullptr, Dd, Dd, 0, 0,0,0,0, 0);

  // 13) LN2
  ln_h<<<Bb*Lq, 256>>>(x, ln2g, ln2b, xn);

  // 14) h = gelu(xn@w1 + b1)
  hgemm<M_GELU><<<dim3(Ff/128,(Bb*Lq)/128,1),256>>>(
      xn, w1t, nullptr,nullptr, b1, nullptr,nullptr, nullptr, nullptr,nullptr,
      nullptr, h, Ff, Dd, 0, 0,0,0,0, 0);

  // 15) out = h@w2 + b2 + x
  hgemm<M_RES><<<dim3(Dd/128,(Bb*Lq)/128,1),256>>>(
      h, w2t, nullptr,nullptr, b2, nullptr,nullptr, x, nullptr,nullptr,
      out, nullptr, Dd, Ff, 0, 0,0,0,0, 0);
}